// round 2
// baseline (speedup 1.0000x reference)
#include <cuda_runtime.h>
#include <math.h>

#define N_TOK   49
#define C_DIM   96
#define H_NUM   3
#define HD      32
#define PAIRS   (N_TOK * H_NUM)   // 147
#define THREADS 160

typedef unsigned long long u64;

// MLP-generated relative position bias, shared by all windows: [H][N][N]
__device__ float g_bias[H_NUM * N_TOK * N_TOK];

// ---- packed f32x2 helpers (sm_100+) ---------------------------------------
__device__ __forceinline__ u64 ffma2(u64 a, u64 b, u64 c) {
    u64 d;
    asm("fma.rn.f32x2 %0, %1, %2, %3;" : "=l"(d) : "l"(a), "l"(b), "l"(c));
    return d;
}
__device__ __forceinline__ u64 fadd2(u64 a, u64 b) {
    u64 d;
    asm("add.rn.f32x2 %0, %1, %2;" : "=l"(d) : "l"(a), "l"(b));
    return d;
}
__device__ __forceinline__ u64 pack2(float x) {
    u64 r;
    asm("mov.b64 %0, {%1, %1};" : "=l"(r) : "f"(x));
    return r;
}
__device__ __forceinline__ float2 unpack2(u64 a) {
    float lo, hi;
    asm("mov.b64 {%0, %1}, %2;" : "=f"(lo), "=f"(hi) : "l"(a));
    return make_float2(lo, hi);
}

// ---------------------------------------------------------------------------
// Kernel 1: bias = relu(rel_pos @ w1 + b1) @ w2 + b2    (2401 positions)
// ---------------------------------------------------------------------------
__global__ void bias_kernel(const float* __restrict__ rel_pos,
                            const float* __restrict__ w1,
                            const float* __restrict__ b1,
                            const float* __restrict__ w2,
                            const float* __restrict__ b2) {
    int p = blockIdx.x * blockDim.x + threadIdx.x;
    if (p >= N_TOK * N_TOK) return;
    float r0 = rel_pos[p * 2 + 0];
    float r1 = rel_pos[p * 2 + 1];
    float acc0 = b2[0], acc1 = b2[1], acc2 = b2[2];
    #pragma unroll 8
    for (int j = 0; j < 256; ++j) {
        float hj = fmaf(r0, w1[j], fmaf(r1, w1[256 + j], b1[j]));
        hj = fmaxf(hj, 0.0f);
        acc0 = fmaf(hj, w2[j * 3 + 0], acc0);
        acc1 = fmaf(hj, w2[j * 3 + 1], acc1);
        acc2 = fmaf(hj, w2[j * 3 + 2], acc2);
    }
    g_bias[0 * (N_TOK * N_TOK) + p] = acc0;
    g_bias[1 * (N_TOK * N_TOK) + p] = acc1;
    g_bias[2 * (N_TOK * N_TOK) + p] = acc2;
}

// ---------------------------------------------------------------------------
// Kernel 2: window attention. One CTA per window.
// Thread t -> pair (h = t/49, n = t%49) for t < 147.
// One kv smem buffer, staged with k for pass 1 then v for pass 2.
// Scores live in smem (conflict-free column layout), probs never stored:
// exp + sum fused into the PV pass, o normalized at the end.
// ---------------------------------------------------------------------------
__global__ __launch_bounds__(THREADS, 4)
void attn_kernel(const float* __restrict__ q,
                 const float* __restrict__ k,
                 const float* __restrict__ v,
                 float*       __restrict__ out) {
    __shared__ __align__(16) float kv[N_TOK * C_DIM];   // 18816 B
    __shared__ float ss[N_TOK * PAIRS];                  // 28812 B

    const int b = blockIdx.x;
    const int t = threadIdx.x;
    const size_t wbase = (size_t)b * (N_TOK * C_DIM);

    // ---- stage K ----
    {
        const float4* k4 = (const float4*)(k + wbase);
        float4* kv4 = (float4*)kv;
        #pragma unroll
        for (int i = t; i < (N_TOK * C_DIM) / 4; i += THREADS)
            kv4[i] = k4[i];
    }
    __syncthreads();

    const bool valid = (t < PAIRS);
    const int h = t / N_TOK;
    const int n = t - h * N_TOK;

    // per-thread query row as 16 packed f32x2
    u64 qr[HD / 2];
    if (valid) {
        const ulonglong2* qp = (const ulonglong2*)(q + wbase + n * C_DIM + h * HD);
        #pragma unroll
        for (int i = 0; i < 8; ++i) {
            ulonglong2 x = qp[i];
            qr[2 * i + 0] = x.x;
            qr[2 * i + 1] = x.y;
        }
    }

    const float scale = 0.17677669529663687f;  // 1/sqrt(32)
    float mx = -1e30f;

    // ---- pass 1: scores -> smem, track max ----
    if (valid) {
        const float* bp = g_bias + (h * N_TOK + n) * N_TOK;
        #pragma unroll 7
        for (int m = 0; m < N_TOK; ++m) {
            const ulonglong2* kp = (const ulonglong2*)(kv + m * C_DIM + h * HD);
            u64 accA = 0ull, accB = 0ull;
            #pragma unroll
            for (int i = 0; i < 8; ++i) {
                ulonglong2 x = kp[i];
                accA = ffma2(qr[2 * i + 0], x.x, accA);
                accB = ffma2(qr[2 * i + 1], x.y, accB);
            }
            float2 d2 = unpack2(fadd2(accA, accB));
            float sc = fmaf(d2.x + d2.y, scale, __ldg(bp + m));
            ss[m * PAIRS + t] = sc;
            mx = fmaxf(mx, sc);
        }
    }
    __syncthreads();

    // ---- stage V (same buffer) ----
    {
        const float4* v4 = (const float4*)(v + wbase);
        float4* kv4 = (float4*)kv;
        #pragma unroll
        for (int i = t; i < (N_TOK * C_DIM) / 4; i += THREADS)
            kv4[i] = v4[i];
    }
    __syncthreads();

    // ---- pass 2: fused exp + sum + PV ----
    if (valid) {
        u64 o[HD / 2];
        #pragma unroll
        for (int i = 0; i < HD / 2; ++i) o[i] = 0ull;

        float sum = 0.0f;
        #pragma unroll 7
        for (int m = 0; m < N_TOK; ++m) {
            float e = __expf(ss[m * PAIRS + t] - mx);
            sum += e;
            u64 ep = pack2(e);
            const ulonglong2* vp = (const ulonglong2*)(kv + m * C_DIM + h * HD);
            #pragma unroll
            for (int i = 0; i < 8; ++i) {
                ulonglong2 x = vp[i];
                o[2 * i + 0] = ffma2(ep, x.x, o[2 * i + 0]);
                o[2 * i + 1] = ffma2(ep, x.y, o[2 * i + 1]);
            }
        }

        const u64 invp = pack2(1.0f / sum);
        float* op = out + wbase + n * C_DIM + h * HD;
        #pragma unroll
        for (int i = 0; i < 8; ++i) {
            float2 a = unpack2(ffma2(o[2 * i + 0], invp, 0ull));
            float2 c = unpack2(ffma2(o[2 * i + 1], invp, 0ull));
            *(float4*)(op + 4 * i) = make_float4(a.x, a.y, c.x, c.y);
        }
    }
}

// ---------------------------------------------------------------------------
extern "C" void kernel_launch(void* const* d_in, const int* in_sizes, int n_in,
                              void* d_out, int out_size) {
    const float* q       = (const float*)d_in[0];
    const float* k       = (const float*)d_in[1];
    const float* v       = (const float*)d_in[2];
    const float* rel_pos = (const float*)d_in[3];
    const float* w1      = (const float*)d_in[4];
    const float* b1      = (const float*)d_in[5];
    const float* w2      = (const float*)d_in[6];
    const float* b2      = (const float*)d_in[7];
    float* out = (float*)d_out;

    const int nwin = in_sizes[0] / (N_TOK * C_DIM);

    bias_kernel<<<(N_TOK * N_TOK + 127) / 128, 128>>>(rel_pos, w1, b1, w2, b2);
    attn_kernel<<<nwin, THREADS>>>(q, k, v, out);
}

// round 3
// speedup vs baseline: 1.2697x; 1.2697x over previous
#include <cuda_runtime.h>
#include <math.h>

#define N_TOK   49
#define C_DIM   96
#define THREADS 192

// smem layout (float offsets)
#define QT_D    66        // per-d stride (even -> LDS.64 aligned)
#define QT_H    2120      // per-head stride (mod 32 == 8 -> staging bank spread)
#define KT_BASE 6360
#define ET_H    4096      // e_t: [h][m 0..63][n 0..63] (+XOR swizzle)
#define V_BASE  12720
#define V_H     1572
#define SMEM_FLOATS 17436 // 69744 bytes

typedef unsigned long long u64;

__device__ float g_bias[3 * 64 * 64];   // zero-padded [h][n64][m64]

// ---- packed f32x2 helpers ---------------------------------------------------
__device__ __forceinline__ u64 ffma2(u64 a, u64 b, u64 c) {
    u64 d; asm("fma.rn.f32x2 %0, %1, %2, %3;" : "=l"(d) : "l"(a), "l"(b), "l"(c));
    return d;
}
__device__ __forceinline__ u64 pack2(float x) {
    u64 r; asm("mov.b64 %0, {%1, %1};" : "=l"(r) : "f"(x)); return r;
}
__device__ __forceinline__ u64 pk2(float lo, float hi) {
    u64 r; asm("mov.b64 %0, {%1, %2};" : "=l"(r) : "f"(lo), "f"(hi)); return r;
}
__device__ __forceinline__ float2 unpack2(u64 a) {
    float lo, hi; asm("mov.b64 {%0, %1}, %2;" : "=f"(lo), "=f"(hi) : "l"(a));
    return make_float2(lo, hi);
}

// ---------------------------------------------------------------------------
// Kernel 1: zero-padded bias table [3][64][64]; valid (n<49, m<49) from MLP.
// ---------------------------------------------------------------------------
__global__ void bias_kernel(const float* __restrict__ rel_pos,
                            const float* __restrict__ w1,
                            const float* __restrict__ b1,
                            const float* __restrict__ w2,
                            const float* __restrict__ b2) {
    int p = blockIdx.x * blockDim.x + threadIdx.x;
    if (p >= 64 * 64) return;
    int n = p >> 6, m = p & 63;
    float acc0 = 0.f, acc1 = 0.f, acc2 = 0.f;
    if (n < N_TOK && m < N_TOK) {
        int idx = n * N_TOK + m;
        float r0 = rel_pos[2 * idx + 0];
        float r1 = rel_pos[2 * idx + 1];
        acc0 = b2[0]; acc1 = b2[1]; acc2 = b2[2];
        #pragma unroll 8
        for (int j = 0; j < 256; ++j) {
            float hj = fmaf(r0, w1[j], fmaf(r1, w1[256 + j], b1[j]));
            hj = fmaxf(hj, 0.0f);
            acc0 = fmaf(hj, w2[j * 3 + 0], acc0);
            acc1 = fmaf(hj, w2[j * 3 + 1], acc1);
            acc2 = fmaf(hj, w2[j * 3 + 2], acc2);
        }
    }
    g_bias[0 * 4096 + p] = acc0;
    g_bias[1 * 4096 + p] = acc1;
    g_bias[2 * 4096 + p] = acc2;
}

// ---------------------------------------------------------------------------
// Kernel 2: register-tiled window attention. CTA = 1 window, 6 warps.
// warp -> (h = w>>1, n-half = w&1). QK lanes: 4(n-grp) x 8(m-grp), tile 8x8.
// PV lanes: 4(n-grp) x 8(d-grp), tile 8n x 4d.
// ---------------------------------------------------------------------------
__global__ __launch_bounds__(THREADS, 3)
void attn_kernel(const float* __restrict__ q,
                 const float* __restrict__ k,
                 const float* __restrict__ v,
                 float*       __restrict__ out) {
    extern __shared__ float S[];

    const int b    = blockIdx.x;
    const int tid  = threadIdx.x;
    const int lane = tid & 31;
    const int warp = tid >> 5;
    const int h    = warp >> 1;
    const int nb   = (warp & 1) * 32;
    const int ng   = lane >> 3;
    const int mg   = lane & 7;       // also d-group in PV
    const size_t wbase = (size_t)b * (N_TOK * C_DIM);

    // ---- stage q (scaled, transposed), k (transposed), v (row-major) ----
    {
        const float SCALE = 0.17677669529663687f;  // 1/sqrt(32)
        const float4* qg = (const float4*)q + (size_t)b * 1176;
        const float4* kg = (const float4*)k + (size_t)b * 1176;
        const float4* vg = (const float4*)v + (size_t)b * 1176;
        for (int i = tid; i < 1176; i += THREADS) {
            int n  = i / 24;
            int c4 = i - n * 24;
            int hh = c4 >> 3;
            int d0 = (c4 & 7) * 4;
            float4 qv = qg[i];
            float4 kv = kg[i];
            float4 vv = vg[i];
            float* qd = S + hh * QT_H + n;
            qd[(d0 + 0) * QT_D] = qv.x * SCALE;
            qd[(d0 + 1) * QT_D] = qv.y * SCALE;
            qd[(d0 + 2) * QT_D] = qv.z * SCALE;
            qd[(d0 + 3) * QT_D] = qv.w * SCALE;
            float* kd = S + KT_BASE + hh * QT_H + n;
            kd[(d0 + 0) * QT_D] = kv.x;
            kd[(d0 + 1) * QT_D] = kv.y;
            kd[(d0 + 2) * QT_D] = kv.z;
            kd[(d0 + 3) * QT_D] = kv.w;
            *(float4*)(S + V_BASE + hh * V_H + n * 32 + d0) = vv;
        }
    }
    __syncthreads();

    // ---- QK: acc[np][j] = f32x2 over n-pair, scalar over m ----
    u64 acc[4][8];
    #pragma unroll
    for (int a = 0; a < 4; ++a)
        #pragma unroll
        for (int j = 0; j < 8; ++j) acc[a][j] = 0ull;

    {
        const float* qrow0 = S + h * QT_H + nb + 8 * ng;
        const float* krow0 = S + KT_BASE + h * QT_H + 8 * mg;
        #pragma unroll 8
        for (int d = 0; d < 32; ++d) {
            const float* qr = qrow0 + d * QT_D;
            const float* kr = krow0 + d * QT_D;
            u64 qp[4];
            #pragma unroll
            for (int np = 0; np < 4; ++np)
                qp[np] = *(const u64*)(qr + 2 * np);
            #pragma unroll
            for (int t = 0; t < 4; ++t) {
                float2 kf = unpack2(*(const u64*)(kr + 2 * t));
                u64 kb0 = pack2(kf.x);
                u64 kb1 = pack2(kf.y);
                #pragma unroll
                for (int np = 0; np < 4; ++np) {
                    acc[np][2 * t + 0] = ffma2(qp[np], kb0, acc[np][2 * t + 0]);
                    acc[np][2 * t + 1] = ffma2(qp[np], kb1, acc[np][2 * t + 1]);
                }
            }
        }
    }
    __syncthreads();   // all q_t/k_t reads done before e_t overlay

    // ---- softmax (rows n) + store unnormalized e to swizzled e_t ----
    float inv[8];
    {
        const int sig = 2 * (mg & 3);
        float* et = S + h * ET_H + 512 * mg + nb + 8 * ng;  // + 64*j + (2np^sig)
        #pragma unroll
        for (int np = 0; np < 4; ++np) {
            int n0 = nb + 8 * ng + 2 * np;
            float sa[8], sb[8];
            #pragma unroll
            for (int j = 0; j < 8; ++j) {
                float2 t2 = unpack2(acc[np][j]);
                sa[j] = t2.x; sb[j] = t2.y;
            }
            const float4* ba = (const float4*)(g_bias + h * 4096 + n0 * 64 + 8 * mg);
            const float4* bb = (const float4*)(g_bias + h * 4096 + (n0 + 1) * 64 + 8 * mg);
            float4 a0 = __ldg(ba), a1 = __ldg(ba + 1);
            float4 c0 = __ldg(bb), c1 = __ldg(bb + 1);
            sa[0] += a0.x; sa[1] += a0.y; sa[2] += a0.z; sa[3] += a0.w;
            sa[4] += a1.x; sa[5] += a1.y; sa[6] += a1.z; sa[7] += a1.w;
            sb[0] += c0.x; sb[1] += c0.y; sb[2] += c0.z; sb[3] += c0.w;
            sb[4] += c1.x; sb[5] += c1.y; sb[6] += c1.z; sb[7] += c1.w;
            #pragma unroll
            for (int j = 0; j < 8; ++j) {
                if (8 * mg + j >= N_TOK) { sa[j] = -1e30f; sb[j] = -1e30f; }
            }
            float mxa = sa[0], mxb = sb[0];
            #pragma unroll
            for (int j = 1; j < 8; ++j) { mxa = fmaxf(mxa, sa[j]); mxb = fmaxf(mxb, sb[j]); }
            #pragma unroll
            for (int o = 1; o < 8; o <<= 1) {
                mxa = fmaxf(mxa, __shfl_xor_sync(0xffffffffu, mxa, o));
                mxb = fmaxf(mxb, __shfl_xor_sync(0xffffffffu, mxb, o));
            }
            float suma = 0.f, sumb = 0.f;
            float ea[8], eb[8];
            #pragma unroll
            for (int j = 0; j < 8; ++j) {
                ea[j] = __expf(sa[j] - mxa); suma += ea[j];
                eb[j] = __expf(sb[j] - mxb); sumb += eb[j];
            }
            #pragma unroll
            for (int o = 1; o < 8; o <<= 1) {
                suma += __shfl_xor_sync(0xffffffffu, suma, o);
                sumb += __shfl_xor_sync(0xffffffffu, sumb, o);
            }
            inv[2 * np + 0] = 1.0f / suma;
            inv[2 * np + 1] = 1.0f / sumb;
            const int tnp = (2 * np) ^ sig;
            #pragma unroll
            for (int j = 0; j < 8; ++j)
                *(u64*)(et + 64 * j + tnp) = pk2(ea[j], eb[j]);
        }
    }
    __syncthreads();

    // ---- PV: o[np][d'] f32x2 over n-pair; lanes 4(n) x 8(d-grp) ----
    {
        const int dg = mg;
        u64 o[4][4];
        #pragma unroll
        for (int a = 0; a < 4; ++a)
            #pragma unroll
            for (int c = 0; c < 4; ++c) o[a][c] = 0ull;

        const float* vb  = S + V_BASE + h * V_H + 4 * dg;
        const float* eb0 = S + h * ET_H + nb + 8 * ng;
        #pragma unroll 7
        for (int m = 0; m < N_TOK; ++m) {
            const int sg = 2 * ((m >> 3) & 3);
            const float* em = eb0 + m * 64;
            u64 ep[4];
            #pragma unroll
            for (int np = 0; np < 4; ++np)
                ep[np] = *(const u64*)(em + ((2 * np) ^ sg));
            float4 vv = *(const float4*)(vb + m * 32);
            u64 v0 = pack2(vv.x), v1 = pack2(vv.y), v2 = pack2(vv.z), v3 = pack2(vv.w);
            #pragma unroll
            for (int np = 0; np < 4; ++np) {
                o[np][0] = ffma2(ep[np], v0, o[np][0]);
                o[np][1] = ffma2(ep[np], v1, o[np][1]);
                o[np][2] = ffma2(ep[np], v2, o[np][2]);
                o[np][3] = ffma2(ep[np], v3, o[np][3]);
            }
        }

        // epilogue: normalize rows, store float4 per row
        #pragma unroll
        for (int np = 0; np < 4; ++np) {
            float2 u0 = unpack2(o[np][0]);
            float2 u1 = unpack2(o[np][1]);
            float2 u2 = unpack2(o[np][2]);
            float2 u3 = unpack2(o[np][3]);
            int nA = nb + 8 * ng + 2 * np;
            if (nA < N_TOK) {
                float iv = inv[2 * np + 0];
                *(float4*)(out + wbase + nA * C_DIM + h * 32 + 4 * dg) =
                    make_float4(u0.x * iv, u1.x * iv, u2.x * iv, u3.x * iv);
            }
            int nB = nA + 1;
            if (nB < N_TOK) {
                float iv = inv[2 * np + 1];
                *(float4*)(out + wbase + nB * C_DIM + h * 32 + 4 * dg) =
                    make_float4(u0.y * iv, u1.y * iv, u2.y * iv, u3.y * iv);
            }
        }
    }
}

// ---------------------------------------------------------------------------
extern "C" void kernel_launch(void* const* d_in, const int* in_sizes, int n_in,
                              void* d_out, int out_size) {
    const float* q       = (const float*)d_in[0];
    const float* k       = (const float*)d_in[1];
    const float* v       = (const float*)d_in[2];
    const float* rel_pos = (const float*)d_in[3];
    const float* w1      = (const float*)d_in[4];
    const float* b1      = (const float*)d_in[5];
    const float* w2      = (const float*)d_in[6];
    const float* b2      = (const float*)d_in[7];
    float* out = (float*)d_out;

    const int nwin = in_sizes[0] / (N_TOK * C_DIM);
    const int smem_bytes = SMEM_FLOATS * 4;

    cudaFuncSetAttribute(attn_kernel,
                         cudaFuncAttributeMaxDynamicSharedMemorySize, smem_bytes);

    bias_kernel<<<(64 * 64 + 127) / 128, 128>>>(rel_pos, w1, b1, w2, b2);
    attn_kernel<<<nwin, THREADS, smem_bytes>>>(q, k, v, out);
}

// round 5
// speedup vs baseline: 2.0315x; 1.5999x over previous
#include <cuda_runtime.h>
#include <cuda_bf16.h>
#include <cstdint>

#define N_TOK 49
#define C_DIM 96

// smem byte offsets (dynamic)
#define QHI 0
#define QLO 5120
#define KHI 10240
#define KLO 15360
#define VHI 20480
#define VLO 25600
#define EHI 30720
#define ELO 39936
#define SMEM_BYTES 49152
#define RS 80     // q/k/v row stride (32 bf16 = 64B data + 16B pad)
#define ES 144    // e row stride (64 bf16 = 128B data + 16B pad)

__device__ float g_bias[3 * 64 * 64];   // [h][n64][m64], m>=49 -> -1e30

// ---------------------------------------------------------------------------
__device__ __forceinline__ uint32_t smem_u32(const void* p) {
    uint32_t a;
    asm("{ .reg .u64 t; cvta.to.shared.u64 t, %1; cvt.u32.u64 %0, t; }" : "=r"(a) : "l"(p));
    return a;
}
__device__ __forceinline__ void ldsm4(uint32_t r[4], uint32_t addr) {
    asm volatile("ldmatrix.sync.aligned.m8n8.x4.shared.b16 {%0,%1,%2,%3}, [%4];"
                 : "=r"(r[0]), "=r"(r[1]), "=r"(r[2]), "=r"(r[3]) : "r"(addr));
}
__device__ __forceinline__ void ldsm4t(uint32_t r[4], uint32_t addr) {
    asm volatile("ldmatrix.sync.aligned.m8n8.x4.trans.shared.b16 {%0,%1,%2,%3}, [%4];"
                 : "=r"(r[0]), "=r"(r[1]), "=r"(r[2]), "=r"(r[3]) : "r"(addr));
}
__device__ __forceinline__ void mma16816(float c[4], const uint32_t a[4],
                                         uint32_t b0, uint32_t b1) {
    asm volatile(
        "mma.sync.aligned.m16n8k16.row.col.f32.bf16.bf16.f32 "
        "{%0,%1,%2,%3}, {%4,%5,%6,%7}, {%8,%9}, {%0,%1,%2,%3};"
        : "+f"(c[0]), "+f"(c[1]), "+f"(c[2]), "+f"(c[3])
        : "r"(a[0]), "r"(a[1]), "r"(a[2]), "r"(a[3]), "r"(b0), "r"(b1));
}
// split x into bf16 hi + bf16 lo (x ~= hi + lo), packed pairs
__device__ __forceinline__ void cvt2(float x, float y, uint32_t& hi, uint32_t& lo) {
    __nv_bfloat162 h = __floats2bfloat162_rn(x, y);
    float hx = __bfloat162float(__low2bfloat16(h));
    float hy = __bfloat162float(__high2bfloat16(h));
    __nv_bfloat162 l = __floats2bfloat162_rn(x - hx, y - hy);
    hi = *reinterpret_cast<uint32_t*>(&h);
    lo = *reinterpret_cast<uint32_t*>(&l);
}

// ---------------------------------------------------------------------------
__global__ void bias_kernel(const float* __restrict__ rel_pos,
                            const float* __restrict__ w1,
                            const float* __restrict__ b1,
                            const float* __restrict__ w2,
                            const float* __restrict__ b2) {
    int p = blockIdx.x * blockDim.x + threadIdx.x;
    if (p >= 64 * 64) return;
    int n = p >> 6, m = p & 63;
    float acc0, acc1, acc2;
    if (m >= N_TOK) {
        acc0 = acc1 = acc2 = -1e30f;          // mask pad columns
    } else if (n >= N_TOK) {
        acc0 = acc1 = acc2 = 0.0f;            // pad rows: value irrelevant
    } else {
        int idx = n * N_TOK + m;
        float r0 = rel_pos[2 * idx + 0];
        float r1 = rel_pos[2 * idx + 1];
        acc0 = b2[0]; acc1 = b2[1]; acc2 = b2[2];
        #pragma unroll 8
        for (int j = 0; j < 256; ++j) {
            float hj = fmaf(r0, w1[j], fmaf(r1, w1[256 + j], b1[j]));
            hj = fmaxf(hj, 0.0f);
            acc0 = fmaf(hj, w2[j * 3 + 0], acc0);
            acc1 = fmaf(hj, w2[j * 3 + 1], acc1);
            acc2 = fmaf(hj, w2[j * 3 + 2], acc2);
        }
    }
    g_bias[0 * 4096 + p] = acc0;
    g_bias[1 * 4096 + p] = acc1;
    g_bias[2 * 4096 + p] = acc2;
}

// ---------------------------------------------------------------------------
// CTA = 1 window, 4 warps (warp = 16-row M-tile), loop over 3 heads.
// QK: m16n8k16 bf16 hi/lo (3 terms). Softmax in registers (quad shuffles).
// e -> smem bf16 hi/lo -> PV mma. Bias table provides -inf masking.
// ---------------------------------------------------------------------------
__global__ __launch_bounds__(128, 4)
void attn_kernel(const float* __restrict__ q,
                 const float* __restrict__ k,
                 const float* __restrict__ v,
                 float*       __restrict__ out) {
    extern __shared__ __align__(16) char S[];
    const uint32_t sb = smem_u32(S);

    const int tid  = threadIdx.x;
    const int lane = tid & 31;
    const int warp = tid >> 5;
    const int g    = lane >> 2;          // row-in-8 group
    const int tig  = lane & 3;           // thread in group
    const int r0   = warp * 16;          // warp's M-tile base row
    const int POFF = (lane & 7) + 8 * ((lane >> 3) & 1);  // ldmatrix row-in-16
    const int CG   = lane >> 4;                            // ldmatrix col group
    const size_t wbase = (size_t)blockIdx.x * (N_TOK * C_DIM);

    for (int h = 0; h < 3; ++h) {
        __syncthreads();   // previous head fully consumed smem

        // ---- stage q(scaled)/k/v as bf16 hi/lo; zero pad rows 49..63 ----
        {
            const float SC = 0.17677669529663687f;  // 1/sqrt(32)
            #pragma unroll
            for (int it = 0; it < 4; ++it) {
                int i = tid + it * 128;             // 512 = 64 rows x 8 chunks
                int n = i >> 3, c = i & 7;
                uint32_t off = (uint32_t)(n * RS + c * 8);
                uint2 qh = make_uint2(0, 0), ql = qh, kh = qh, kl = qh, vh = qh, vl = qh;
                if (n < N_TOK) {
                    size_t ga = wbase + (size_t)n * C_DIM + h * 32 + c * 4;
                    float4 xq = *(const float4*)(q + ga);
                    float4 xk = *(const float4*)(k + ga);
                    float4 xv = *(const float4*)(v + ga);
                    cvt2(xq.x * SC, xq.y * SC, qh.x, ql.x);
                    cvt2(xq.z * SC, xq.w * SC, qh.y, ql.y);
                    cvt2(xk.x, xk.y, kh.x, kl.x);
                    cvt2(xk.z, xk.w, kh.y, kl.y);
                    cvt2(xv.x, xv.y, vh.x, vl.x);
                    cvt2(xv.z, xv.w, vh.y, vl.y);
                }
                *(uint2*)(S + QHI + off) = qh;  *(uint2*)(S + QLO + off) = ql;
                *(uint2*)(S + KHI + off) = kh;  *(uint2*)(S + KLO + off) = kl;
                *(uint2*)(S + VHI + off) = vh;  *(uint2*)(S + VLO + off) = vl;
            }
        }
        __syncthreads();

        // ---- QK: S[64x64] = q @ k^T  (hi*hi + lo*hi + hi*lo) ----
        float acc[8][4];
        #pragma unroll
        for (int j = 0; j < 8; ++j)
            #pragma unroll
            for (int c = 0; c < 4; ++c) acc[j][c] = 0.0f;

        {
            uint32_t qh0[4], qh1[4], ql0[4], ql1[4];
            const uint32_t aP = sb + QHI + (uint32_t)((r0 + POFF) * RS + CG * 16);
            ldsm4(qh0, aP);
            ldsm4(qh1, aP + 32);
            ldsm4(ql0, aP + (QLO - QHI));
            ldsm4(ql1, aP + (QLO - QHI) + 32);

            const uint32_t bP = sb + KHI + (uint32_t)((lane & 7) * RS + (lane >> 3) * 16);
            #pragma unroll
            for (int j = 0; j < 8; ++j) {
                uint32_t bh[4], bl[4];
                ldsm4(bh, bP + (uint32_t)(j * 8 * RS));
                mma16816(acc[j], qh0, bh[0], bh[1]);
                mma16816(acc[j], qh1, bh[2], bh[3]);
                mma16816(acc[j], ql0, bh[0], bh[1]);
                mma16816(acc[j], ql1, bh[2], bh[3]);
                ldsm4(bl, bP + (uint32_t)(j * 8 * RS) + (KLO - KHI));
                mma16816(acc[j], qh0, bl[0], bl[1]);
                mma16816(acc[j], qh1, bl[2], bl[3]);
            }
        }

        // ---- softmax: rows n1 = r0+g, n2 = r0+g+8 (quad-local) ----
        const int n1 = r0 + g, n2 = r0 + g + 8;
        float s1[16], s2[16];
        {
            const float* bb = g_bias + h * 4096;
            #pragma unroll
            for (int j = 0; j < 8; ++j) {
                float2 b1 = *(const float2*)(bb + n1 * 64 + 8 * j + 2 * tig);
                float2 b2 = *(const float2*)(bb + n2 * 64 + 8 * j + 2 * tig);
                s1[2 * j + 0] = acc[j][0] + b1.x;
                s1[2 * j + 1] = acc[j][1] + b1.y;
                s2[2 * j + 0] = acc[j][2] + b2.x;
                s2[2 * j + 1] = acc[j][3] + b2.y;
            }
        }
        float mx1 = s1[0], mx2 = s2[0];
        #pragma unroll
        for (int i = 1; i < 16; ++i) { mx1 = fmaxf(mx1, s1[i]); mx2 = fmaxf(mx2, s2[i]); }
        mx1 = fmaxf(mx1, __shfl_xor_sync(0xffffffffu, mx1, 1));
        mx1 = fmaxf(mx1, __shfl_xor_sync(0xffffffffu, mx1, 2));
        mx2 = fmaxf(mx2, __shfl_xor_sync(0xffffffffu, mx2, 1));
        mx2 = fmaxf(mx2, __shfl_xor_sync(0xffffffffu, mx2, 2));
        float sum1 = 0.0f, sum2 = 0.0f;
        #pragma unroll
        for (int i = 0; i < 16; ++i) {
            s1[i] = __expf(s1[i] - mx1); sum1 += s1[i];
            s2[i] = __expf(s2[i] - mx2); sum2 += s2[i];
        }
        sum1 += __shfl_xor_sync(0xffffffffu, sum1, 1);
        sum1 += __shfl_xor_sync(0xffffffffu, sum1, 2);
        sum2 += __shfl_xor_sync(0xffffffffu, sum2, 1);
        sum2 += __shfl_xor_sync(0xffffffffu, sum2, 2);
        const float rinv1 = 1.0f / sum1;
        const float rinv2 = 1.0f / sum2;

        // ---- store e (unnormalized) as bf16 hi/lo ----
        {
            const uint32_t e1P = sb + EHI + (uint32_t)(n1 * ES + tig * 4);
            const uint32_t e2P = sb + EHI + (uint32_t)(n2 * ES + tig * 4);
            #pragma unroll
            for (int j = 0; j < 8; ++j) {
                uint32_t hi, lo;
                cvt2(s1[2 * j], s1[2 * j + 1], hi, lo);
                *(uint32_t*)(S + (e1P - sb) + j * 16) = hi;
                *(uint32_t*)(S + (e1P - sb) + (ELO - EHI) + j * 16) = lo;
                cvt2(s2[2 * j], s2[2 * j + 1], hi, lo);
                *(uint32_t*)(S + (e2P - sb) + j * 16) = hi;
                *(uint32_t*)(S + (e2P - sb) + (ELO - EHI) + j * 16) = lo;
            }
        }
        __syncwarp();   // cross-lane smem visibility before ldmatrix

        // ---- PV: O[64x32] = e @ v  (hi*hi + lo*hi + hi*lo) ----
        float o[4][4];
        #pragma unroll
        for (int j = 0; j < 4; ++j)
            #pragma unroll
            for (int c = 0; c < 4; ++c) o[j][c] = 0.0f;

        {
            uint32_t eh[4][4], el[4][4];
            const uint32_t eP = sb + EHI + (uint32_t)((r0 + POFF) * ES + CG * 16);
            #pragma unroll
            for (int ks = 0; ks < 4; ++ks) {
                ldsm4(eh[ks], eP + ks * 32);
                ldsm4(el[ks], eP + ks * 32 + (ELO - EHI));
            }
            const uint32_t vP = sb + VHI + (uint32_t)(POFF * RS + CG * 16);
            #pragma unroll
            for (int ks = 0; ks < 4; ++ks) {
                uint32_t va[4], vb[4];
                const uint32_t base = vP + (uint32_t)(ks * 16 * RS);
                ldsm4t(va, base);
                ldsm4t(vb, base + 32);
                mma16816(o[0], eh[ks], va[0], va[1]);
                mma16816(o[1], eh[ks], va[2], va[3]);
                mma16816(o[2], eh[ks], vb[0], vb[1]);
                mma16816(o[3], eh[ks], vb[2], vb[3]);
                mma16816(o[0], el[ks], va[0], va[1]);
                mma16816(o[1], el[ks], va[2], va[3]);
                mma16816(o[2], el[ks], vb[0], vb[1]);
                mma16816(o[3], el[ks], vb[2], vb[3]);
                ldsm4t(va, base + (VLO - VHI));
                ldsm4t(vb, base + (VLO - VHI) + 32);
                mma16816(o[0], eh[ks], va[0], va[1]);
                mma16816(o[1], eh[ks], va[2], va[3]);
                mma16816(o[2], eh[ks], vb[0], vb[1]);
                mma16816(o[3], eh[ks], vb[2], vb[3]);
            }
        }

        // ---- normalize + store ----
        if (n1 < N_TOK) {
            float* op = out + wbase + (size_t)n1 * C_DIM + h * 32;
            #pragma unroll
            for (int j = 0; j < 4; ++j)
                *(float2*)(op + 8 * j + 2 * tig) =
                    make_float2(o[j][0] * rinv1, o[j][1] * rinv1);
        }
        if (n2 < N_TOK) {
            float* op = out + wbase + (size_t)n2 * C_DIM + h * 32;
            #pragma unroll
            for (int j = 0; j < 4; ++j)
                *(float2*)(op + 8 * j + 2 * tig) =
                    make_float2(o[j][2] * rinv2, o[j][3] * rinv2);
        }
    }
}

// ---------------------------------------------------------------------------
extern "C" void kernel_launch(void* const* d_in, const int* in_sizes, int n_in,
                              void* d_out, int out_size) {
    const float* q       = (const float*)d_in[0];
    const float* k       = (const float*)d_in[1];
    const float* v       = (const float*)d_in[2];
    const float* rel_pos = (const float*)d_in[3];
    const float* w1      = (const float*)d_in[4];
    const float* b1      = (const float*)d_in[5];
    const float* w2      = (const float*)d_in[6];
    const float* b2      = (const float*)d_in[7];
    float* out = (float*)d_out;

    const int nwin = in_sizes[0] / (N_TOK * C_DIM);

    cudaFuncSetAttribute(attn_kernel,
                         cudaFuncAttributeMaxDynamicSharedMemorySize, SMEM_BYTES);

    bias_kernel<<<(64 * 64 + 127) / 128, 128>>>(rel_pos, w1, b1, w2, b2);
    attn_kernel<<<nwin, 128, SMEM_BYTES>>>(q, k, v, out);
}

// round 6
// speedup vs baseline: 2.0576x; 1.0129x over previous
#include <cuda_runtime.h>
#include <cuda_bf16.h>
#include <cstdint>

#define N_TOK 49
#define C_DIM 96
#define RS 80          // k/v row stride bytes (64B data + 16B pad)
#define KHI 0
#define KLO 5120
#define VHI 10240
#define VLO 15360
#define SMEM_BYTES 20480

__device__ float g_bias[3 * 64 * 64];   // [h][n64][m64], m>=49 -> -1e30

// ---------------------------------------------------------------------------
__device__ __forceinline__ uint32_t smem_u32(const void* p) {
    uint32_t a;
    asm("{ .reg .u64 t; cvta.to.shared.u64 t, %1; cvt.u32.u64 %0, t; }" : "=r"(a) : "l"(p));
    return a;
}
__device__ __forceinline__ void ldsm4(uint32_t r[4], uint32_t addr) {
    asm volatile("ldmatrix.sync.aligned.m8n8.x4.shared.b16 {%0,%1,%2,%3}, [%4];"
                 : "=r"(r[0]), "=r"(r[1]), "=r"(r[2]), "=r"(r[3]) : "r"(addr));
}
__device__ __forceinline__ void ldsm4t(uint32_t r[4], uint32_t addr) {
    asm volatile("ldmatrix.sync.aligned.m8n8.x4.trans.shared.b16 {%0,%1,%2,%3}, [%4];"
                 : "=r"(r[0]), "=r"(r[1]), "=r"(r[2]), "=r"(r[3]) : "r"(addr));
}
__device__ __forceinline__ void mma16816(float c[4], const uint32_t a[4],
                                         uint32_t b0, uint32_t b1) {
    asm volatile(
        "mma.sync.aligned.m16n8k16.row.col.f32.bf16.bf16.f32 "
        "{%0,%1,%2,%3}, {%4,%5,%6,%7}, {%8,%9}, {%0,%1,%2,%3};"
        : "+f"(c[0]), "+f"(c[1]), "+f"(c[2]), "+f"(c[3])
        : "r"(a[0]), "r"(a[1]), "r"(a[2]), "r"(a[3]), "r"(b0), "r"(b1));
}
// split (x,y) into packed bf16 hi + bf16 lo (x ~= hi + lo)
__device__ __forceinline__ void cvt2(float x, float y, uint32_t& hi, uint32_t& lo) {
    __nv_bfloat162 h = __floats2bfloat162_rn(x, y);
    float hx = __bfloat162float(__low2bfloat16(h));
    float hy = __bfloat162float(__high2bfloat16(h));
    __nv_bfloat162 l = __floats2bfloat162_rn(x - hx, y - hy);
    hi = *reinterpret_cast<uint32_t*>(&h);
    lo = *reinterpret_cast<uint32_t*>(&l);
}

// ---------------------------------------------------------------------------
__global__ void bias_kernel(const float* __restrict__ rel_pos,
                            const float* __restrict__ w1,
                            const float* __restrict__ b1,
                            const float* __restrict__ w2,
                            const float* __restrict__ b2) {
    int p = blockIdx.x * blockDim.x + threadIdx.x;
    if (p >= 64 * 64) return;
    int n = p >> 6, m = p & 63;
    float acc0, acc1, acc2;
    if (m >= N_TOK) {
        acc0 = acc1 = acc2 = -1e30f;          // mask pad columns
    } else if (n >= N_TOK) {
        acc0 = acc1 = acc2 = 0.0f;            // pad rows: value irrelevant
    } else {
        int idx = n * N_TOK + m;
        float r0 = rel_pos[2 * idx + 0];
        float r1 = rel_pos[2 * idx + 1];
        acc0 = b2[0]; acc1 = b2[1]; acc2 = b2[2];
        #pragma unroll 8
        for (int j = 0; j < 256; ++j) {
            float hj = fmaf(r0, w1[j], fmaf(r1, w1[256 + j], b1[j]));
            hj = fmaxf(hj, 0.0f);
            acc0 = fmaf(hj, w2[j * 3 + 0], acc0);
            acc1 = fmaf(hj, w2[j * 3 + 1], acc1);
            acc2 = fmaf(hj, w2[j * 3 + 2], acc2);
        }
    }
    g_bias[0 * 4096 + p] = acc0;
    g_bias[1 * 4096 + p] = acc1;
    g_bias[2 * 4096 + p] = acc2;
}

// ---------------------------------------------------------------------------
// CTA = (window, head). 4 warps, warp = 16-row M-tile.
// q: direct global -> A fragments (registers). k,v: smem + ldmatrix.
// e: stays in registers (softmax layout == PV A-fragment layout).
// ---------------------------------------------------------------------------
__global__ __launch_bounds__(128, 4)
void attn_kernel(const float* __restrict__ q,
                 const float* __restrict__ k,
                 const float* __restrict__ v,
                 float*       __restrict__ out) {
    __shared__ __align__(16) char S[SMEM_BYTES];
    const uint32_t sb = smem_u32(S);

    const int tid  = threadIdx.x;
    const int lane = tid & 31;
    const int warp = tid >> 5;
    const int g    = lane >> 2;
    const int tig  = lane & 3;
    const int r0   = warp * 16;
    const int POFF = (lane & 7) + 8 * ((lane >> 3) & 1);
    const int CG   = lane >> 4;
    const int h    = blockIdx.y;
    const size_t wbase = (size_t)blockIdx.x * (N_TOK * C_DIM);

    // ---- stage k, v as bf16 hi/lo; zero pad rows 49..63 ----
    #pragma unroll
    for (int it = 0; it < 4; ++it) {
        int i = tid + it * 128;            // 512 = 64 rows x 8 chunks
        int n = i >> 3, c = i & 7;
        uint32_t off = (uint32_t)(n * RS + c * 8);
        uint2 kh = make_uint2(0, 0), kl = kh, vh = kh, vl = kh;
        if (n < N_TOK) {
            size_t ga = wbase + (size_t)n * C_DIM + h * 32 + c * 4;
            float4 xk = *(const float4*)(k + ga);
            float4 xv = *(const float4*)(v + ga);
            cvt2(xk.x, xk.y, kh.x, kl.x);
            cvt2(xk.z, xk.w, kh.y, kl.y);
            cvt2(xv.x, xv.y, vh.x, vl.x);
            cvt2(xv.z, xv.w, vh.y, vl.y);
        }
        *(uint2*)(S + KHI + off) = kh;  *(uint2*)(S + KLO + off) = kl;
        *(uint2*)(S + VHI + off) = vh;  *(uint2*)(S + VLO + off) = vl;
    }

    // ---- q A-fragments straight from global (overlap with staging) ----
    const int n1 = r0 + g, n2 = n1 + 8;
    uint32_t qh[2][4], ql[2][4];
    {
        const float SC = 0.17677669529663687f;  // 1/sqrt(32)
        const float* qp1 = q + wbase + (size_t)n1 * C_DIM + h * 32;
        const float* qp2 = q + wbase + (size_t)n2 * C_DIM + h * 32;
        const bool v1 = (n1 < N_TOK), v2 = (n2 < N_TOK);
        #pragma unroll
        for (int t = 0; t < 2; ++t) {
            #pragma unroll
            for (int hf = 0; hf < 2; ++hf) {
                int cc = 16 * t + 8 * hf + 2 * tig;
                float2 a = v1 ? *(const float2*)(qp1 + cc) : make_float2(0.f, 0.f);
                float2 b = v2 ? *(const float2*)(qp2 + cc) : make_float2(0.f, 0.f);
                cvt2(a.x * SC, a.y * SC, qh[t][2 * hf + 0], ql[t][2 * hf + 0]);
                cvt2(b.x * SC, b.y * SC, qh[t][2 * hf + 1], ql[t][2 * hf + 1]);
            }
        }
    }
    __syncthreads();

    // ---- QK: S[64x64] = q @ k^T  (hi*hi + lo*hi + hi*lo) ----
    float acc[8][4];
    #pragma unroll
    for (int j = 0; j < 8; ++j)
        #pragma unroll
        for (int c = 0; c < 4; ++c) acc[j][c] = 0.0f;

    {
        const uint32_t bP = sb + KHI + (uint32_t)((lane & 7) * RS + (lane >> 3) * 16);
        #pragma unroll
        for (int j = 0; j < 8; ++j) {
            uint32_t bh[4], bl[4];
            ldsm4(bh, bP + (uint32_t)(j * 8 * RS));
            mma16816(acc[j], qh[0], bh[0], bh[1]);
            mma16816(acc[j], qh[1], bh[2], bh[3]);
            mma16816(acc[j], ql[0], bh[0], bh[1]);
            mma16816(acc[j], ql[1], bh[2], bh[3]);
            ldsm4(bl, bP + (uint32_t)(j * 8 * RS) + (KLO - KHI));
            mma16816(acc[j], qh[0], bl[0], bl[1]);
            mma16816(acc[j], qh[1], bl[2], bl[3]);
        }
    }

    // ---- softmax rows n1, n2 (quad-local) ----
    float s1[16], s2[16];
    {
        const float* bb = g_bias + h * 4096;
        #pragma unroll
        for (int j = 0; j < 8; ++j) {
            float2 b1 = *(const float2*)(bb + n1 * 64 + 8 * j + 2 * tig);
            float2 b2 = *(const float2*)(bb + n2 * 64 + 8 * j + 2 * tig);
            s1[2 * j + 0] = acc[j][0] + b1.x;
            s1[2 * j + 1] = acc[j][1] + b1.y;
            s2[2 * j + 0] = acc[j][2] + b2.x;
            s2[2 * j + 1] = acc[j][3] + b2.y;
        }
    }
    float mx1 = s1[0], mx2 = s2[0];
    #pragma unroll
    for (int i = 1; i < 16; ++i) { mx1 = fmaxf(mx1, s1[i]); mx2 = fmaxf(mx2, s2[i]); }
    mx1 = fmaxf(mx1, __shfl_xor_sync(0xffffffffu, mx1, 1));
    mx1 = fmaxf(mx1, __shfl_xor_sync(0xffffffffu, mx1, 2));
    mx2 = fmaxf(mx2, __shfl_xor_sync(0xffffffffu, mx2, 1));
    mx2 = fmaxf(mx2, __shfl_xor_sync(0xffffffffu, mx2, 2));
    float sum1 = 0.0f, sum2 = 0.0f;
    #pragma unroll
    for (int i = 0; i < 16; ++i) {
        s1[i] = __expf(s1[i] - mx1); sum1 += s1[i];
        s2[i] = __expf(s2[i] - mx2); sum2 += s2[i];
    }
    sum1 += __shfl_xor_sync(0xffffffffu, sum1, 1);
    sum1 += __shfl_xor_sync(0xffffffffu, sum1, 2);
    sum2 += __shfl_xor_sync(0xffffffffu, sum2, 1);
    sum2 += __shfl_xor_sync(0xffffffffu, sum2, 2);
    const float rinv1 = 1.0f / sum1;
    const float rinv2 = 1.0f / sum2;

    // ---- e A-fragments built in registers (no smem round trip) ----
    uint32_t eh[4][4], el[4][4];
    #pragma unroll
    for (int t = 0; t < 4; ++t) {
        cvt2(s1[4 * t + 0], s1[4 * t + 1], eh[t][0], el[t][0]);
        cvt2(s2[4 * t + 0], s2[4 * t + 1], eh[t][1], el[t][1]);
        cvt2(s1[4 * t + 2], s1[4 * t + 3], eh[t][2], el[t][2]);
        cvt2(s2[4 * t + 2], s2[4 * t + 3], eh[t][3], el[t][3]);
    }

    // ---- PV: O[64x32] = e @ v  (hi*hi + lo*hi + hi*lo) ----
    float o[4][4];
    #pragma unroll
    for (int j = 0; j < 4; ++j)
        #pragma unroll
        for (int c = 0; c < 4; ++c) o[j][c] = 0.0f;

    {
        const uint32_t vP = sb + VHI + (uint32_t)(POFF * RS + CG * 16);
        #pragma unroll
        for (int t = 0; t < 4; ++t) {
            uint32_t va[4], vb[4];
            const uint32_t base = vP + (uint32_t)(t * 16 * RS);
            ldsm4t(va, base);
            ldsm4t(vb, base + 32);
            mma16816(o[0], eh[t], va[0], va[1]);
            mma16816(o[1], eh[t], va[2], va[3]);
            mma16816(o[2], eh[t], vb[0], vb[1]);
            mma16816(o[3], eh[t], vb[2], vb[3]);
            mma16816(o[0], el[t], va[0], va[1]);
            mma16816(o[1], el[t], va[2], va[3]);
            mma16816(o[2], el[t], vb[0], vb[1]);
            mma16816(o[3], el[t], vb[2], vb[3]);
            ldsm4t(va, base + (VLO - VHI));
            ldsm4t(vb, base + (VLO - VHI) + 32);
            mma16816(o[0], eh[t], va[0], va[1]);
            mma16816(o[1], eh[t], va[2], va[3]);
            mma16816(o[2], eh[t], vb[0], vb[1]);
            mma16816(o[3], eh[t], vb[2], vb[3]);
        }
    }

    // ---- normalize + store ----
    if (n1 < N_TOK) {
        float* op = out + wbase + (size_t)n1 * C_DIM + h * 32;
        #pragma unroll
        for (int j = 0; j < 4; ++j)
            *(float2*)(op + 8 * j + 2 * tig) =
                make_float2(o[j][0] * rinv1, o[j][1] * rinv1);
    }
    if (n2 < N_TOK) {
        float* op = out + wbase + (size_t)n2 * C_DIM + h * 32;
        #pragma unroll
        for (int j = 0; j < 4; ++j)
            *(float2*)(op + 8 * j + 2 * tig) =
                make_float2(o[j][2] * rinv2, o[j][3] * rinv2);
    }
}

// ---------------------------------------------------------------------------
extern "C" void kernel_launch(void* const* d_in, const int* in_sizes, int n_in,
                              void* d_out, int out_size) {
    const float* q       = (const float*)d_in[0];
    const float* k       = (const float*)d_in[1];
    const float* v       = (const float*)d_in[2];
    const float* rel_pos = (const float*)d_in[3];
    const float* w1      = (const float*)d_in[4];
    const float* b1      = (const float*)d_in[5];
    const float* w2      = (const float*)d_in[6];
    const float* b2      = (const float*)d_in[7];
    float* out = (float*)d_out;

    const int nwin = in_sizes[0] / (N_TOK * C_DIM);

    bias_kernel<<<(64 * 64 + 127) / 128, 128>>>(rel_pos, w1, b1, w2, b2);
    dim3 grid(nwin, 3);
    attn_kernel<<<grid, 128>>>(q, k, v, out);
}

// round 7
// speedup vs baseline: 2.3100x; 1.1226x over previous
#include <cuda_runtime.h>
#include <cuda_bf16.h>
#include <cstdint>

#define N_TOK 49
#define C_DIM 96
#define RS 80          // k/v row stride bytes (64B data + 16B pad)
#define KHI 0
#define KLO 5120
#define VHI 10240
#define VLO 15360
#define SMEM_BYTES 20480

__device__ float g_bias[3 * 64 * 64];   // [h][n64][m64], m>=49 -> -1e30

// ---------------------------------------------------------------------------
__device__ __forceinline__ uint32_t smem_u32(const void* p) {
    uint32_t a;
    asm("{ .reg .u64 t; cvta.to.shared.u64 t, %1; cvt.u32.u64 %0, t; }" : "=r"(a) : "l"(p));
    return a;
}
__device__ __forceinline__ void ldsm4(uint32_t r[4], uint32_t addr) {
    asm volatile("ldmatrix.sync.aligned.m8n8.x4.shared.b16 {%0,%1,%2,%3}, [%4];"
                 : "=r"(r[0]), "=r"(r[1]), "=r"(r[2]), "=r"(r[3]) : "r"(addr));
}
__device__ __forceinline__ void ldsm4t(uint32_t r[4], uint32_t addr) {
    asm volatile("ldmatrix.sync.aligned.m8n8.x4.trans.shared.b16 {%0,%1,%2,%3}, [%4];"
                 : "=r"(r[0]), "=r"(r[1]), "=r"(r[2]), "=r"(r[3]) : "r"(addr));
}
__device__ __forceinline__ void mma16816(float c[4], const uint32_t a[4],
                                         uint32_t b0, uint32_t b1) {
    asm volatile(
        "mma.sync.aligned.m16n8k16.row.col.f32.bf16.bf16.f32 "
        "{%0,%1,%2,%3}, {%4,%5,%6,%7}, {%8,%9}, {%0,%1,%2,%3};"
        : "+f"(c[0]), "+f"(c[1]), "+f"(c[2]), "+f"(c[3])
        : "r"(a[0]), "r"(a[1]), "r"(a[2]), "r"(a[3]), "r"(b0), "r"(b1));
}
// split (x,y) into packed bf16 hi + bf16 lo (x ~= hi + lo)
__device__ __forceinline__ void cvt2(float x, float y, uint32_t& hi, uint32_t& lo) {
    __nv_bfloat162 h = __floats2bfloat162_rn(x, y);
    float hx = __bfloat162float(__low2bfloat16(h));
    float hy = __bfloat162float(__high2bfloat16(h));
    __nv_bfloat162 l = __floats2bfloat162_rn(x - hx, y - hy);
    hi = *reinterpret_cast<uint32_t*>(&h);
    lo = *reinterpret_cast<uint32_t*>(&l);
}

// ---------------------------------------------------------------------------
__global__ void bias_kernel(const float* __restrict__ rel_pos,
                            const float* __restrict__ w1,
                            const float* __restrict__ b1,
                            const float* __restrict__ w2,
                            const float* __restrict__ b2) {
    int p = blockIdx.x * blockDim.x + threadIdx.x;
    if (p >= 64 * 64) return;
    int n = p >> 6, m = p & 63;
    float acc0, acc1, acc2;
    if (m >= N_TOK) {
        acc0 = acc1 = acc2 = -1e30f;          // mask pad columns
    } else if (n >= N_TOK) {
        acc0 = acc1 = acc2 = 0.0f;            // pad rows: value irrelevant
    } else {
        int idx = n * N_TOK + m;
        float r0 = rel_pos[2 * idx + 0];
        float r1 = rel_pos[2 * idx + 1];
        acc0 = b2[0]; acc1 = b2[1]; acc2 = b2[2];
        #pragma unroll 8
        for (int j = 0; j < 256; ++j) {
            float hj = fmaf(r0, w1[j], fmaf(r1, w1[256 + j], b1[j]));
            hj = fmaxf(hj, 0.0f);
            acc0 = fmaf(hj, w2[j * 3 + 0], acc0);
            acc1 = fmaf(hj, w2[j * 3 + 1], acc1);
            acc2 = fmaf(hj, w2[j * 3 + 2], acc2);
        }
    }
    g_bias[0 * 4096 + p] = acc0;
    g_bias[1 * 4096 + p] = acc1;
    g_bias[2 * 4096 + p] = acc2;
}

// ---------------------------------------------------------------------------
// CTA = (window, head). 4 warps, warp = 16-row M-tile.
// q: direct global -> A fragments. k,v: smem + ldmatrix. e: registers only.
// j=7 column block (cols 56..63) is all-pad -> skipped entirely.
// ---------------------------------------------------------------------------
__global__ __launch_bounds__(128, 5)
void attn_kernel(const float* __restrict__ q,
                 const float* __restrict__ k,
                 const float* __restrict__ v,
                 float*       __restrict__ out) {
    __shared__ __align__(16) char S[SMEM_BYTES];
    const uint32_t sb = smem_u32(S);

    const int tid  = threadIdx.x;
    const int lane = tid & 31;
    const int warp = tid >> 5;
    const int g    = lane >> 2;
    const int tig  = lane & 3;
    const int r0   = warp * 16;
    const int POFF = (lane & 7) + 8 * ((lane >> 3) & 1);
    const int CG   = lane >> 4;
    const int h    = blockIdx.y;
    const size_t wbase = (size_t)blockIdx.x * (N_TOK * C_DIM);

    // ---- stage k, v as bf16 hi/lo; zero pad rows 49..63 ----
    #pragma unroll
    for (int it = 0; it < 4; ++it) {
        int i = tid + it * 128;            // 512 = 64 rows x 8 chunks
        int n = i >> 3, c = i & 7;
        uint32_t off = (uint32_t)(n * RS + c * 8);
        uint2 kh = make_uint2(0, 0), kl = kh, vh = kh, vl = kh;
        if (n < N_TOK) {
            size_t ga = wbase + (size_t)n * C_DIM + h * 32 + c * 4;
            float4 xk = *(const float4*)(k + ga);
            float4 xv = *(const float4*)(v + ga);
            cvt2(xk.x, xk.y, kh.x, kl.x);
            cvt2(xk.z, xk.w, kh.y, kl.y);
            cvt2(xv.x, xv.y, vh.x, vl.x);
            cvt2(xv.z, xv.w, vh.y, vl.y);
        }
        *(uint2*)(S + KHI + off) = kh;  *(uint2*)(S + KLO + off) = kl;
        *(uint2*)(S + VHI + off) = vh;  *(uint2*)(S + VLO + off) = vl;
    }

    // ---- q A-fragments straight from global (overlap with staging) ----
    const int n1 = r0 + g, n2 = n1 + 8;
    uint32_t qh[2][4], ql[2][4];
    {
        const float SC = 0.17677669529663687f;  // 1/sqrt(32)
        const float* qp1 = q + wbase + (size_t)n1 * C_DIM + h * 32;
        const float* qp2 = q + wbase + (size_t)n2 * C_DIM + h * 32;
        const bool v1 = (n1 < N_TOK), v2 = (n2 < N_TOK);
        #pragma unroll
        for (int t = 0; t < 2; ++t) {
            #pragma unroll
            for (int hf = 0; hf < 2; ++hf) {
                int cc = 16 * t + 8 * hf + 2 * tig;
                float2 a = v1 ? *(const float2*)(qp1 + cc) : make_float2(0.f, 0.f);
                float2 b = v2 ? *(const float2*)(qp2 + cc) : make_float2(0.f, 0.f);
                cvt2(a.x * SC, a.y * SC, qh[t][2 * hf + 0], ql[t][2 * hf + 0]);
                cvt2(b.x * SC, b.y * SC, qh[t][2 * hf + 1], ql[t][2 * hf + 1]);
            }
        }
    }
    __syncthreads();

    // ---- QK: S[64x56] = q @ k^T  (hi*hi + lo*hi + hi*lo); j=7 all-pad ----
    float acc[7][4];
    #pragma unroll
    for (int j = 0; j < 7; ++j)
        #pragma unroll
        for (int c = 0; c < 4; ++c) acc[j][c] = 0.0f;

    {
        const uint32_t bP = sb + KHI + (uint32_t)((lane & 7) * RS + (lane >> 3) * 16);
        #pragma unroll
        for (int j = 0; j < 7; ++j) {
            uint32_t bh[4], bl[4];
            ldsm4(bh, bP + (uint32_t)(j * 8 * RS));
            mma16816(acc[j], qh[0], bh[0], bh[1]);
            mma16816(acc[j], qh[1], bh[2], bh[3]);
            mma16816(acc[j], ql[0], bh[0], bh[1]);
            mma16816(acc[j], ql[1], bh[2], bh[3]);
            ldsm4(bl, bP + (uint32_t)(j * 8 * RS) + (KLO - KHI));
            mma16816(acc[j], qh[0], bl[0], bl[1]);
            mma16816(acc[j], qh[1], bl[2], bl[3]);
        }
    }

    // ---- softmax rows n1, n2 (quad-local); cols 0..55 live, 56..63 = 0 ----
    float s1[14], s2[14];
    {
        const float* bb = g_bias + h * 4096;
        #pragma unroll
        for (int j = 0; j < 7; ++j) {
            float2 b1 = *(const float2*)(bb + n1 * 64 + 8 * j + 2 * tig);
            float2 b2 = *(const float2*)(bb + n2 * 64 + 8 * j + 2 * tig);
            s1[2 * j + 0] = acc[j][0] + b1.x;
            s1[2 * j + 1] = acc[j][1] + b1.y;
            s2[2 * j + 0] = acc[j][2] + b2.x;
            s2[2 * j + 1] = acc[j][3] + b2.y;
        }
    }
    float mx1 = s1[0], mx2 = s2[0];
    #pragma unroll
    for (int i = 1; i < 14; ++i) { mx1 = fmaxf(mx1, s1[i]); mx2 = fmaxf(mx2, s2[i]); }
    mx1 = fmaxf(mx1, __shfl_xor_sync(0xffffffffu, mx1, 1));
    mx1 = fmaxf(mx1, __shfl_xor_sync(0xffffffffu, mx1, 2));
    mx2 = fmaxf(mx2, __shfl_xor_sync(0xffffffffu, mx2, 1));
    mx2 = fmaxf(mx2, __shfl_xor_sync(0xffffffffu, mx2, 2));
    float sum1 = 0.0f, sum2 = 0.0f;
    #pragma unroll
    for (int i = 0; i < 14; ++i) {
        s1[i] = __expf(s1[i] - mx1); sum1 += s1[i];
        s2[i] = __expf(s2[i] - mx2); sum2 += s2[i];
    }
    sum1 += __shfl_xor_sync(0xffffffffu, sum1, 1);
    sum1 += __shfl_xor_sync(0xffffffffu, sum1, 2);
    sum2 += __shfl_xor_sync(0xffffffffu, sum2, 1);
    sum2 += __shfl_xor_sync(0xffffffffu, sum2, 2);
    const float rinv1 = 1.0f / sum1;
    const float rinv2 = 1.0f / sum2;

    // ---- e A-fragments in registers (cols 56..63 -> zero) ----
    uint32_t eh[4][4], el[4][4];
    #pragma unroll
    for (int t = 0; t < 3; ++t) {
        cvt2(s1[4 * t + 0], s1[4 * t + 1], eh[t][0], el[t][0]);
        cvt2(s2[4 * t + 0], s2[4 * t + 1], eh[t][1], el[t][1]);
        cvt2(s1[4 * t + 2], s1[4 * t + 3], eh[t][2], el[t][2]);
        cvt2(s2[4 * t + 2], s2[4 * t + 3], eh[t][3], el[t][3]);
    }
    cvt2(s1[12], s1[13], eh[3][0], el[3][0]);
    cvt2(s2[12], s2[13], eh[3][1], el[3][1]);
    eh[3][2] = 0u; el[3][2] = 0u;
    eh[3][3] = 0u; el[3][3] = 0u;

    // ---- PV: O[64x32] = e @ v  (hi*hi + lo*hi + hi*lo) ----
    float o[4][4];
    #pragma unroll
    for (int j = 0; j < 4; ++j)
        #pragma unroll
        for (int c = 0; c < 4; ++c) o[j][c] = 0.0f;

    {
        const uint32_t vP = sb + VHI + (uint32_t)(POFF * RS + CG * 16);
        #pragma unroll
        for (int t = 0; t < 4; ++t) {
            uint32_t va[4], vb[4];
            const uint32_t base = vP + (uint32_t)(t * 16 * RS);
            ldsm4t(va, base);
            ldsm4t(vb, base + 32);
            mma16816(o[0], eh[t], va[0], va[1]);
            mma16816(o[1], eh[t], va[2], va[3]);
            mma16816(o[2], eh[t], vb[0], vb[1]);
            mma16816(o[3], eh[t], vb[2], vb[3]);
            mma16816(o[0], el[t], va[0], va[1]);
            mma16816(o[1], el[t], va[2], va[3]);
            mma16816(o[2], el[t], vb[0], vb[1]);
            mma16816(o[3], el[t], vb[2], vb[3]);
            ldsm4t(va, base + (VLO - VHI));
            ldsm4t(vb, base + (VLO - VHI) + 32);
            mma16816(o[0], eh[t], va[0], va[1]);
            mma16816(o[1], eh[t], va[2], va[3]);
            mma16816(o[2], eh[t], vb[0], vb[1]);
            mma16816(o[3], eh[t], vb[2], vb[3]);
        }
    }

    // ---- normalize + store ----
    if (n1 < N_TOK) {
        float* op = out + wbase + (size_t)n1 * C_DIM + h * 32;
        #pragma unroll
        for (int j = 0; j < 4; ++j)
            *(float2*)(op + 8 * j + 2 * tig) =
                make_float2(o[j][0] * rinv1, o[j][1] * rinv1);
    }
    if (n2 < N_TOK) {
        float* op = out + wbase + (size_t)n2 * C_DIM + h * 32;
        #pragma unroll
        for (int j = 0; j < 4; ++j)
            *(float2*)(op + 8 * j + 2 * tig) =
                make_float2(o[j][2] * rinv2, o[j][3] * rinv2);
    }
}

// ---------------------------------------------------------------------------
extern "C" void kernel_launch(void* const* d_in, const int* in_sizes, int n_in,
                              void* d_out, int out_size) {
    const float* q       = (const float*)d_in[0];
    const float* k       = (const float*)d_in[1];
    const float* v       = (const float*)d_in[2];
    const float* rel_pos = (const float*)d_in[3];
    const float* w1      = (const float*)d_in[4];
    const float* b1      = (const float*)d_in[5];
    const float* w2      = (const float*)d_in[6];
    const float* b2      = (const float*)d_in[7];
    float* out = (float*)d_out;

    const int nwin = in_sizes[0] / (N_TOK * C_DIM);

    bias_kernel<<<(64 * 64 + 127) / 128, 128>>>(rel_pos, w1, b1, w2, b2);
    dim3 grid(nwin, 3);
    attn_kernel<<<grid, 128>>>(q, k, v, out);
}

// round 8
// speedup vs baseline: 2.5485x; 1.1033x over previous
#include <cuda_runtime.h>
#include <cuda_bf16.h>
#include <cstdint>

#define N_TOK 49
#define C_DIM 96
#define RS 80          // k/v row stride bytes (64B data + 16B pad)
#define KHI 0
#define KLO 5120
#define VHI 10240
#define VLO 15360
#define SMEM_BYTES 20480

__device__ float g_bias[3 * 64 * 64];   // [h][n64][m64], m>=49 -> -1e30

// ---------------------------------------------------------------------------
__device__ __forceinline__ uint32_t smem_u32(const void* p) {
    uint32_t a;
    asm("{ .reg .u64 t; cvta.to.shared.u64 t, %1; cvt.u32.u64 %0, t; }" : "=r"(a) : "l"(p));
    return a;
}
__device__ __forceinline__ void ldsm4(uint32_t r[4], uint32_t addr) {
    asm volatile("ldmatrix.sync.aligned.m8n8.x4.shared.b16 {%0,%1,%2,%3}, [%4];"
                 : "=r"(r[0]), "=r"(r[1]), "=r"(r[2]), "=r"(r[3]) : "r"(addr));
}
__device__ __forceinline__ void ldsm4t(uint32_t r[4], uint32_t addr) {
    asm volatile("ldmatrix.sync.aligned.m8n8.x4.trans.shared.b16 {%0,%1,%2,%3}, [%4];"
                 : "=r"(r[0]), "=r"(r[1]), "=r"(r[2]), "=r"(r[3]) : "r"(addr));
}
__device__ __forceinline__ void mma16816(float c[4], const uint32_t a[4],
                                         uint32_t b0, uint32_t b1) {
    asm volatile(
        "mma.sync.aligned.m16n8k16.row.col.f32.bf16.bf16.f32 "
        "{%0,%1,%2,%3}, {%4,%5,%6,%7}, {%8,%9}, {%0,%1,%2,%3};"
        : "+f"(c[0]), "+f"(c[1]), "+f"(c[2]), "+f"(c[3])
        : "r"(a[0]), "r"(a[1]), "r"(a[2]), "r"(a[3]), "r"(b0), "r"(b1));
}
// split (x,y) into packed bf16 hi + bf16 lo (x ~= hi + lo)
__device__ __forceinline__ void cvt2(float x, float y, uint32_t& hi, uint32_t& lo) {
    __nv_bfloat162 h = __floats2bfloat162_rn(x, y);
    float hx = __bfloat162float(__low2bfloat16(h));
    float hy = __bfloat162float(__high2bfloat16(h));
    __nv_bfloat162 l = __floats2bfloat162_rn(x - hx, y - hy);
    hi = *reinterpret_cast<uint32_t*>(&h);
    lo = *reinterpret_cast<uint32_t*>(&l);
}

// ---------------------------------------------------------------------------
__global__ void bias_kernel(const float* __restrict__ rel_pos,
                            const float* __restrict__ w1,
                            const float* __restrict__ b1,
                            const float* __restrict__ w2,
                            const float* __restrict__ b2) {
    int p = blockIdx.x * blockDim.x + threadIdx.x;
    if (p >= 64 * 64) return;
    int n = p >> 6, m = p & 63;
    float acc0, acc1, acc2;
    if (m >= N_TOK) {
        acc0 = acc1 = acc2 = -1e30f;          // mask pad columns
    } else if (n >= N_TOK) {
        acc0 = acc1 = acc2 = 0.0f;            // pad rows: value irrelevant
    } else {
        int idx = n * N_TOK + m;
        float r0 = rel_pos[2 * idx + 0];
        float r1 = rel_pos[2 * idx + 1];
        acc0 = b2[0]; acc1 = b2[1]; acc2 = b2[2];
        #pragma unroll 8
        for (int j = 0; j < 256; ++j) {
            float hj = fmaf(r0, w1[j], fmaf(r1, w1[256 + j], b1[j]));
            hj = fmaxf(hj, 0.0f);
            acc0 = fmaf(hj, w2[j * 3 + 0], acc0);
            acc1 = fmaf(hj, w2[j * 3 + 1], acc1);
            acc2 = fmaf(hj, w2[j * 3 + 2], acc2);
        }
    }
    g_bias[0 * 4096 + p] = acc0;
    g_bias[1 * 4096 + p] = acc1;
    g_bias[2 * 4096 + p] = acc2;
}

// ---------------------------------------------------------------------------
// CTA = (window, head). 4 warps, warp = 16-row M-tile.
// q: direct global -> A fragments. k,v: smem + ldmatrix. e: registers only.
// Bias preloaded as the QK accumulator init (C-fragment layout match).
// j=7 column block (cols 56..63) is all-pad -> skipped entirely.
// ---------------------------------------------------------------------------
__global__ __launch_bounds__(128, 6)
void attn_kernel(const float* __restrict__ q,
                 const float* __restrict__ k,
                 const float* __restrict__ v,
                 float*       __restrict__ out) {
    __shared__ __align__(16) char S[SMEM_BYTES];
    const uint32_t sb = smem_u32(S);

    const int tid  = threadIdx.x;
    const int lane = tid & 31;
    const int warp = tid >> 5;
    const int g    = lane >> 2;
    const int tig  = lane & 3;
    const int r0   = warp * 16;
    const int POFF = (lane & 7) + 8 * ((lane >> 3) & 1);
    const int CG   = lane >> 4;
    const int h    = blockIdx.y;
    const size_t wbase = (size_t)blockIdx.x * (N_TOK * C_DIM);
    const int n1 = r0 + g, n2 = n1 + 8;

    // ---- stage k, v as bf16 hi/lo; zero pad rows 49..63 ----
    #pragma unroll
    for (int it = 0; it < 4; ++it) {
        int i = tid + it * 128;            // 512 = 64 rows x 8 chunks
        int n = i >> 3, c = i & 7;
        uint32_t off = (uint32_t)(n * RS + c * 8);
        uint2 kh = make_uint2(0, 0), kl = kh, vh = kh, vl = kh;
        if (n < N_TOK) {
            size_t ga = wbase + (size_t)n * C_DIM + h * 32 + c * 4;
            float4 xk = *(const float4*)(k + ga);
            float4 xv = *(const float4*)(v + ga);
            cvt2(xk.x, xk.y, kh.x, kl.x);
            cvt2(xk.z, xk.w, kh.y, kl.y);
            cvt2(xv.x, xv.y, vh.x, vl.x);
            cvt2(xv.z, xv.w, vh.y, vl.y);
        }
        *(uint2*)(S + KHI + off) = kh;  *(uint2*)(S + KLO + off) = kl;
        *(uint2*)(S + VHI + off) = vh;  *(uint2*)(S + VLO + off) = vl;
    }

    // ---- q A-fragments straight from global (overlap with staging) ----
    uint32_t qh[2][4], ql[2][4];
    {
        const float SC = 0.17677669529663687f;  // 1/sqrt(32)
        const float* qp1 = q + wbase + (size_t)n1 * C_DIM + h * 32;
        const float* qp2 = q + wbase + (size_t)n2 * C_DIM + h * 32;
        const bool v1 = (n1 < N_TOK), v2 = (n2 < N_TOK);
        #pragma unroll
        for (int t = 0; t < 2; ++t) {
            #pragma unroll
            for (int hf = 0; hf < 2; ++hf) {
                int cc = 16 * t + 8 * hf + 2 * tig;
                float2 a = v1 ? *(const float2*)(qp1 + cc) : make_float2(0.f, 0.f);
                float2 b = v2 ? *(const float2*)(qp2 + cc) : make_float2(0.f, 0.f);
                cvt2(a.x * SC, a.y * SC, qh[t][2 * hf + 0], ql[t][2 * hf + 0]);
                cvt2(b.x * SC, b.y * SC, qh[t][2 * hf + 1], ql[t][2 * hf + 1]);
            }
        }
    }

    // ---- bias -> accumulator init (C-fragment layout), overlaps staging ----
    float acc[7][4];
    {
        const float* bb = g_bias + h * 4096;
        #pragma unroll
        for (int j = 0; j < 7; ++j) {
            float2 b1 = *(const float2*)(bb + n1 * 64 + 8 * j + 2 * tig);
            float2 b2 = *(const float2*)(bb + n2 * 64 + 8 * j + 2 * tig);
            acc[j][0] = b1.x;  acc[j][1] = b1.y;
            acc[j][2] = b2.x;  acc[j][3] = b2.y;
        }
    }
    __syncthreads();

    // ---- QK: S[64x56] = bias + q @ k^T  (hi*hi + lo*hi + hi*lo) ----
    {
        const uint32_t bP = sb + KHI + (uint32_t)((lane & 7) * RS + (lane >> 3) * 16);
        #pragma unroll
        for (int j = 0; j < 7; ++j) {
            uint32_t bh[4], bl[4];
            ldsm4(bh, bP + (uint32_t)(j * 8 * RS));
            mma16816(acc[j], qh[0], bh[0], bh[1]);
            mma16816(acc[j], qh[1], bh[2], bh[3]);
            mma16816(acc[j], ql[0], bh[0], bh[1]);
            mma16816(acc[j], ql[1], bh[2], bh[3]);
            ldsm4(bl, bP + (uint32_t)(j * 8 * RS) + (KLO - KHI));
            mma16816(acc[j], qh[0], bl[0], bl[1]);
            mma16816(acc[j], qh[1], bl[2], bl[3]);
        }
    }

    // ---- softmax in-place on acc (rows n1, n2; quad-local reductions) ----
    float mx1 = acc[0][0], mx2 = acc[0][2];
    #pragma unroll
    for (int j = 0; j < 7; ++j) {
        mx1 = fmaxf(mx1, fmaxf(acc[j][0], acc[j][1]));
        mx2 = fmaxf(mx2, fmaxf(acc[j][2], acc[j][3]));
    }
    mx1 = fmaxf(mx1, __shfl_xor_sync(0xffffffffu, mx1, 1));
    mx1 = fmaxf(mx1, __shfl_xor_sync(0xffffffffu, mx1, 2));
    mx2 = fmaxf(mx2, __shfl_xor_sync(0xffffffffu, mx2, 1));
    mx2 = fmaxf(mx2, __shfl_xor_sync(0xffffffffu, mx2, 2));
    float sum1 = 0.0f, sum2 = 0.0f;
    #pragma unroll
    for (int j = 0; j < 7; ++j) {
        acc[j][0] = __expf(acc[j][0] - mx1); sum1 += acc[j][0];
        acc[j][1] = __expf(acc[j][1] - mx1); sum1 += acc[j][1];
        acc[j][2] = __expf(acc[j][2] - mx2); sum2 += acc[j][2];
        acc[j][3] = __expf(acc[j][3] - mx2); sum2 += acc[j][3];
    }
    sum1 += __shfl_xor_sync(0xffffffffu, sum1, 1);
    sum1 += __shfl_xor_sync(0xffffffffu, sum1, 2);
    sum2 += __shfl_xor_sync(0xffffffffu, sum2, 1);
    sum2 += __shfl_xor_sync(0xffffffffu, sum2, 2);
    const float rinv1 = 1.0f / sum1;
    const float rinv2 = 1.0f / sum2;

    // ---- e A-fragments in registers (cols 56..63 -> zero) ----
    uint32_t eh[4][4], el[4][4];
    #pragma unroll
    for (int t = 0; t < 3; ++t) {
        cvt2(acc[2*t][0],   acc[2*t][1],   eh[t][0], el[t][0]);
        cvt2(acc[2*t][2],   acc[2*t][3],   eh[t][1], el[t][1]);
        cvt2(acc[2*t+1][0], acc[2*t+1][1], eh[t][2], el[t][2]);
        cvt2(acc[2*t+1][2], acc[2*t+1][3], eh[t][3], el[t][3]);
    }
    cvt2(acc[6][0], acc[6][1], eh[3][0], el[3][0]);
    cvt2(acc[6][2], acc[6][3], eh[3][1], el[3][1]);
    eh[3][2] = 0u; el[3][2] = 0u;
    eh[3][3] = 0u; el[3][3] = 0u;

    // ---- PV: O[64x32] = e @ v  (hi*hi + lo*hi + hi*lo) ----
    float o[4][4];
    #pragma unroll
    for (int j = 0; j < 4; ++j)
        #pragma unroll
        for (int c = 0; c < 4; ++c) o[j][c] = 0.0f;

    {
        const uint32_t vP = sb + VHI + (uint32_t)(POFF * RS + CG * 16);
        #pragma unroll
        for (int t = 0; t < 4; ++t) {
            uint32_t va[4], vb[4];
            const uint32_t base = vP + (uint32_t)(t * 16 * RS);
            ldsm4t(va, base);
            ldsm4t(vb, base + 32);
            mma16816(o[0], eh[t], va[0], va[1]);
            mma16816(o[1], eh[t], va[2], va[3]);
            mma16816(o[2], eh[t], vb[0], vb[1]);
            mma16816(o[3], eh[t], vb[2], vb[3]);
            mma16816(o[0], el[t], va[0], va[1]);
            mma16816(o[1], el[t], va[2], va[3]);
            mma16816(o[2], el[t], vb[0], vb[1]);
            mma16816(o[3], el[t], vb[2], vb[3]);
            ldsm4t(va, base + (VLO - VHI));
            ldsm4t(vb, base + (VLO - VHI) + 32);
            mma16816(o[0], eh[t], va[0], va[1]);
            mma16816(o[1], eh[t], va[2], va[3]);
            mma16816(o[2], eh[t], vb[0], vb[1]);
            mma16816(o[3], eh[t], vb[2], vb[3]);
        }
    }

    // ---- normalize + store ----
    if (n1 < N_TOK) {
        float* op = out + wbase + (size_t)n1 * C_DIM + h * 32;
        #pragma unroll
        for (int j = 0; j < 4; ++j)
            *(float2*)(op + 8 * j + 2 * tig) =
                make_float2(o[j][0] * rinv1, o[j][1] * rinv1);
    }
    if (n2 < N_TOK) {
        float* op = out + wbase + (size_t)n2 * C_DIM + h * 32;
        #pragma unroll
        for (int j = 0; j < 4; ++j)
            *(float2*)(op + 8 * j + 2 * tig) =
                make_float2(o[j][2] * rinv2, o[j][3] * rinv2);
    }
}

// ---------------------------------------------------------------------------
extern "C" void kernel_launch(void* const* d_in, const int* in_sizes, int n_in,
                              void* d_out, int out_size) {
    const float* q       = (const float*)d_in[0];
    const float* k       = (const float*)d_in[1];
    const float* v       = (const float*)d_in[2];
    const float* rel_pos = (const float*)d_in[3];
    const float* w1      = (const float*)d_in[4];
    const float* b1      = (const float*)d_in[5];
    const float* w2      = (const float*)d_in[6];
    const float* b2      = (const float*)d_in[7];
    float* out = (float*)d_out;

    const int nwin = in_sizes[0] / (N_TOK * C_DIM);

    bias_kernel<<<(64 * 64 + 127) / 128, 128>>>(rel_pos, w1, b1, w2, b2);
    dim3 grid(nwin, 3);
    attn_kernel<<<grid, 128>>>(q, k, v, out);
}

// round 9
// speedup vs baseline: 3.1109x; 1.2207x over previous
#include <cuda_runtime.h>
#include <cuda_bf16.h>
#include <cstdint>

#define N_TOK 49
#define C_DIM 96
#define RS 80          // row stride bytes (64B data + 16B pad)
#define QHI 0
#define QLO 5120
#define KHI 10240
#define KLO 15360
#define VHI 20480
#define VLO 25600
#define SMEM_BYTES 30720

__device__ float  g_bias[3 * 64 * 64];      // [h][n64][m64], m>=49 -> -1e30
__device__ float4 g_bias4[3 * 4 * 7 * 32];  // C-fragment-ordered bias table

// ---------------------------------------------------------------------------
__device__ __forceinline__ uint32_t smem_u32(const void* p) {
    uint32_t a;
    asm("{ .reg .u64 t; cvta.to.shared.u64 t, %1; cvt.u32.u64 %0, t; }" : "=r"(a) : "l"(p));
    return a;
}
__device__ __forceinline__ void ldsm4(uint32_t r[4], uint32_t addr) {
    asm volatile("ldmatrix.sync.aligned.m8n8.x4.shared.b16 {%0,%1,%2,%3}, [%4];"
                 : "=r"(r[0]), "=r"(r[1]), "=r"(r[2]), "=r"(r[3]) : "r"(addr));
}
__device__ __forceinline__ void ldsm4t(uint32_t r[4], uint32_t addr) {
    asm volatile("ldmatrix.sync.aligned.m8n8.x4.trans.shared.b16 {%0,%1,%2,%3}, [%4];"
                 : "=r"(r[0]), "=r"(r[1]), "=r"(r[2]), "=r"(r[3]) : "r"(addr));
}
__device__ __forceinline__ void mma16816(float c[4], const uint32_t a[4],
                                         uint32_t b0, uint32_t b1) {
    asm volatile(
        "mma.sync.aligned.m16n8k16.row.col.f32.bf16.bf16.f32 "
        "{%0,%1,%2,%3}, {%4,%5,%6,%7}, {%8,%9}, {%0,%1,%2,%3};"
        : "+f"(c[0]), "+f"(c[1]), "+f"(c[2]), "+f"(c[3])
        : "r"(a[0]), "r"(a[1]), "r"(a[2]), "r"(a[3]), "r"(b0), "r"(b1));
}
// split (x,y) into packed bf16 hi + bf16 lo (x ~= hi + lo)
__device__ __forceinline__ void cvt2(float x, float y, uint32_t& hi, uint32_t& lo) {
    __nv_bfloat162 h = __floats2bfloat162_rn(x, y);
    float hx = __bfloat162float(__low2bfloat16(h));
    float hy = __bfloat162float(__high2bfloat16(h));
    __nv_bfloat162 l = __floats2bfloat162_rn(x - hx, y - hy);
    hi = *reinterpret_cast<uint32_t*>(&h);
    lo = *reinterpret_cast<uint32_t*>(&l);
}

// ---------------------------------------------------------------------------
__global__ void bias_kernel(const float* __restrict__ rel_pos,
                            const float* __restrict__ w1,
                            const float* __restrict__ b1,
                            const float* __restrict__ w2,
                            const float* __restrict__ b2) {
    int p = blockIdx.x * blockDim.x + threadIdx.x;
    if (p >= 64 * 64) return;
    int n = p >> 6, m = p & 63;
    float acc0, acc1, acc2;
    if (m >= N_TOK) {
        acc0 = acc1 = acc2 = -1e30f;          // mask pad columns
    } else if (n >= N_TOK) {
        acc0 = acc1 = acc2 = 0.0f;            // pad rows: value irrelevant
    } else {
        int idx = n * N_TOK + m;
        float r0 = rel_pos[2 * idx + 0];
        float r1 = rel_pos[2 * idx + 1];
        acc0 = b2[0]; acc1 = b2[1]; acc2 = b2[2];
        #pragma unroll 8
        for (int j = 0; j < 256; ++j) {
            float hj = fmaf(r0, w1[j], fmaf(r1, w1[256 + j], b1[j]));
            hj = fmaxf(hj, 0.0f);
            acc0 = fmaf(hj, w2[j * 3 + 0], acc0);
            acc1 = fmaf(hj, w2[j * 3 + 1], acc1);
            acc2 = fmaf(hj, w2[j * 3 + 2], acc2);
        }
    }
    g_bias[0 * 4096 + p] = acc0;
    g_bias[1 * 4096 + p] = acc1;
    g_bias[2 * 4096 + p] = acc2;
}

// Gather bias into per-thread C-fragment order: [h][warp][j][lane] -> float4
__global__ void bias_gather_kernel() {
    int p = blockIdx.x * blockDim.x + threadIdx.x;
    if (p >= 3 * 4 * 7 * 32) return;
    int lane = p & 31;
    int t    = p >> 5;            // [0, 84)
    int j    = t % 7;
    int w    = (t / 7) % 4;
    int h    = t / 28;
    int g    = lane >> 2;
    int tig  = lane & 3;
    int n1   = w * 16 + g;
    int n2   = n1 + 8;
    int c0   = 8 * j + 2 * tig;
    const float* bb = g_bias + h * 4096;
    g_bias4[p] = make_float4(bb[n1 * 64 + c0], bb[n1 * 64 + c0 + 1],
                             bb[n2 * 64 + c0], bb[n2 * 64 + c0 + 1]);
}

// ---------------------------------------------------------------------------
// CTA = (window, head). 4 warps, warp = 16-row M-tile.
// q/k/v staged to smem as bf16 hi/lo; all fragments via ldmatrix.
// Bias preloaded coalesced (fragment-ordered table) as accumulator init.
// e stays in registers. j=7 all-pad column block skipped.
// ---------------------------------------------------------------------------
__global__ __launch_bounds__(128, 6)
void attn_kernel(const float* __restrict__ q,
                 const float* __restrict__ k,
                 const float* __restrict__ v,
                 float*       __restrict__ out) {
    __shared__ __align__(16) char S[SMEM_BYTES];
    const uint32_t sb = smem_u32(S);

    const int tid  = threadIdx.x;
    const int lane = tid & 31;
    const int warp = tid >> 5;
    const int g    = lane >> 2;
    const int tig  = lane & 3;
    const int r0   = warp * 16;
    const int POFF = (lane & 7) + 8 * ((lane >> 3) & 1);
    const int CG   = lane >> 4;
    const int h    = blockIdx.y;
    const size_t wbase = (size_t)blockIdx.x * (N_TOK * C_DIM);
    const int n1 = r0 + g, n2 = n1 + 8;

    // ---- stage q (scaled), k, v as bf16 hi/lo; zero pad rows 49..63 ----
    {
        const float SC = 0.17677669529663687f;  // 1/sqrt(32)
        #pragma unroll
        for (int it = 0; it < 4; ++it) {
            int i = tid + it * 128;            // 512 = 64 rows x 8 chunks
            int n = i >> 3, c = i & 7;
            uint32_t off = (uint32_t)(n * RS + c * 8);
            uint2 qh = make_uint2(0, 0), ql = qh, kh = qh, kl = qh, vh = qh, vl = qh;
            if (n < N_TOK) {
                size_t ga = wbase + (size_t)n * C_DIM + h * 32 + c * 4;
                float4 xq = *(const float4*)(q + ga);
                float4 xk = *(const float4*)(k + ga);
                float4 xv = *(const float4*)(v + ga);
                cvt2(xq.x * SC, xq.y * SC, qh.x, ql.x);
                cvt2(xq.z * SC, xq.w * SC, qh.y, ql.y);
                cvt2(xk.x, xk.y, kh.x, kl.x);
                cvt2(xk.z, xk.w, kh.y, kl.y);
                cvt2(xv.x, xv.y, vh.x, vl.x);
                cvt2(xv.z, xv.w, vh.y, vl.y);
            }
            *(uint2*)(S + QHI + off) = qh;  *(uint2*)(S + QLO + off) = ql;
            *(uint2*)(S + KHI + off) = kh;  *(uint2*)(S + KLO + off) = kl;
            *(uint2*)(S + VHI + off) = vh;  *(uint2*)(S + VLO + off) = vl;
        }
    }

    // ---- bias -> accumulator init (coalesced fragment-ordered table) ----
    float acc[7][4];
    {
        const float4* bt = g_bias4 + ((h * 4 + warp) * 7) * 32 + lane;
        #pragma unroll
        for (int j = 0; j < 7; ++j) {
            float4 bv = __ldg(bt + j * 32);
            acc[j][0] = bv.x;  acc[j][1] = bv.y;
            acc[j][2] = bv.z;  acc[j][3] = bv.w;
        }
    }
    __syncthreads();

    // ---- q A-fragments via ldmatrix ----
    uint32_t qh0[4], qh1[4], ql0[4], ql1[4];
    {
        const uint32_t aP = sb + QHI + (uint32_t)((r0 + POFF) * RS + CG * 16);
        ldsm4(qh0, aP);
        ldsm4(qh1, aP + 32);
        ldsm4(ql0, aP + (QLO - QHI));
        ldsm4(ql1, aP + (QLO - QHI) + 32);
    }

    // ---- QK: S[64x56] = bias + q @ k^T  (hi*hi + lo*hi + hi*lo) ----
    {
        const uint32_t bP = sb + KHI + (uint32_t)((lane & 7) * RS + (lane >> 3) * 16);
        #pragma unroll
        for (int j = 0; j < 7; ++j) {
            uint32_t bh[4], bl[4];
            ldsm4(bh, bP + (uint32_t)(j * 8 * RS));
            mma16816(acc[j], qh0, bh[0], bh[1]);
            mma16816(acc[j], qh1, bh[2], bh[3]);
            mma16816(acc[j], ql0, bh[0], bh[1]);
            mma16816(acc[j], ql1, bh[2], bh[3]);
            ldsm4(bl, bP + (uint32_t)(j * 8 * RS) + (KLO - KHI));
            mma16816(acc[j], qh0, bl[0], bl[1]);
            mma16816(acc[j], qh1, bl[2], bl[3]);
        }
    }

    // ---- softmax in-place on acc (rows n1, n2; quad-local reductions) ----
    float mx1 = acc[0][0], mx2 = acc[0][2];
    #pragma unroll
    for (int j = 0; j < 7; ++j) {
        mx1 = fmaxf(mx1, fmaxf(acc[j][0], acc[j][1]));
        mx2 = fmaxf(mx2, fmaxf(acc[j][2], acc[j][3]));
    }
    mx1 = fmaxf(mx1, __shfl_xor_sync(0xffffffffu, mx1, 1));
    mx1 = fmaxf(mx1, __shfl_xor_sync(0xffffffffu, mx1, 2));
    mx2 = fmaxf(mx2, __shfl_xor_sync(0xffffffffu, mx2, 1));
    mx2 = fmaxf(mx2, __shfl_xor_sync(0xffffffffu, mx2, 2));
    float sum1 = 0.0f, sum2 = 0.0f;
    #pragma unroll
    for (int j = 0; j < 7; ++j) {
        acc[j][0] = __expf(acc[j][0] - mx1); sum1 += acc[j][0];
        acc[j][1] = __expf(acc[j][1] - mx1); sum1 += acc[j][1];
        acc[j][2] = __expf(acc[j][2] - mx2); sum2 += acc[j][2];
        acc[j][3] = __expf(acc[j][3] - mx2); sum2 += acc[j][3];
    }
    sum1 += __shfl_xor_sync(0xffffffffu, sum1, 1);
    sum1 += __shfl_xor_sync(0xffffffffu, sum1, 2);
    sum2 += __shfl_xor_sync(0xffffffffu, sum2, 1);
    sum2 += __shfl_xor_sync(0xffffffffu, sum2, 2);
    const float rinv1 = 1.0f / sum1;
    const float rinv2 = 1.0f / sum2;

    // ---- e A-fragments in registers (cols 56..63 -> zero) ----
    uint32_t eh[4][4], el[4][4];
    #pragma unroll
    for (int t = 0; t < 3; ++t) {
        cvt2(acc[2*t][0],   acc[2*t][1],   eh[t][0], el[t][0]);
        cvt2(acc[2*t][2],   acc[2*t][3],   eh[t][1], el[t][1]);
        cvt2(acc[2*t+1][0], acc[2*t+1][1], eh[t][2], el[t][2]);
        cvt2(acc[2*t+1][2], acc[2*t+1][3], eh[t][3], el[t][3]);
    }
    cvt2(acc[6][0], acc[6][1], eh[3][0], el[3][0]);
    cvt2(acc[6][2], acc[6][3], eh[3][1], el[3][1]);
    eh[3][2] = 0u; el[3][2] = 0u;
    eh[3][3] = 0u; el[3][3] = 0u;

    // ---- PV: O[64x32] = e @ v  (hi*hi + lo*hi + hi*lo) ----
    float o[4][4];
    #pragma unroll
    for (int j = 0; j < 4; ++j)
        #pragma unroll
        for (int c = 0; c < 4; ++c) o[j][c] = 0.0f;

    {
        const uint32_t vP = sb + VHI + (uint32_t)(POFF * RS + CG * 16);
        #pragma unroll
        for (int t = 0; t < 4; ++t) {
            uint32_t va[4], vb[4];
            const uint32_t base = vP + (uint32_t)(t * 16 * RS);
            ldsm4t(va, base);
            ldsm4t(vb, base + 32);
            mma16816(o[0], eh[t], va[0], va[1]);
            mma16816(o[1], eh[t], va[2], va[3]);
            mma16816(o[2], eh[t], vb[0], vb[1]);
            mma16816(o[3], eh[t], vb[2], vb[3]);
            mma16816(o[0], el[t], va[0], va[1]);
            mma16816(o[1], el[t], va[2], va[3]);
            mma16816(o[2], el[t], vb[0], vb[1]);
            mma16816(o[3], el[t], vb[2], vb[3]);
            ldsm4t(va, base + (VLO - VHI));
            ldsm4t(vb, base + (VLO - VHI) + 32);
            mma16816(o[0], eh[t], va[0], va[1]);
            mma16816(o[1], eh[t], va[2], va[3]);
            mma16816(o[2], eh[t], vb[0], vb[1]);
            mma16816(o[3], eh[t], vb[2], vb[3]);
        }
    }

    // ---- normalize + store ----
    if (n1 < N_TOK) {
        float* op = out + wbase + (size_t)n1 * C_DIM + h * 32;
        #pragma unroll
        for (int j = 0; j < 4; ++j)
            *(float2*)(op + 8 * j + 2 * tig) =
                make_float2(o[j][0] * rinv1, o[j][1] * rinv1);
    }
    if (n2 < N_TOK) {
        float* op = out + wbase + (size_t)n2 * C_DIM + h * 32;
        #pragma unroll
        for (int j = 0; j < 4; ++j)
            *(float2*)(op + 8 * j + 2 * tig) =
                make_float2(o[j][2] * rinv2, o[j][3] * rinv2);
    }
}

// ---------------------------------------------------------------------------
extern "C" void kernel_launch(void* const* d_in, const int* in_sizes, int n_in,
                              void* d_out, int out_size) {
    const float* q       = (const float*)d_in[0];
    const float* k       = (const float*)d_in[1];
    const float* v       = (const float*)d_in[2];
    const float* rel_pos = (const float*)d_in[3];
    const float* w1      = (const float*)d_in[4];
    const float* b1      = (const float*)d_in[5];
    const float* w2      = (const float*)d_in[6];
    const float* b2      = (const float*)d_in[7];
    float* out = (float*)d_out;

    const int nwin = in_sizes[0] / (N_TOK * C_DIM);

    bias_kernel<<<(64 * 64 + 127) / 128, 128>>>(rel_pos, w1, b1, w2, b2);
    bias_gather_kernel<<<(3 * 4 * 7 * 32 + 127) / 128, 128>>>();
    dim3 grid(nwin, 3);
    attn_kernel<<<grid, 128>>>(q, k, v, out);
}

// round 10
// speedup vs baseline: 3.3131x; 1.0650x over previous
#include <cuda_runtime.h>
#include <cuda_bf16.h>
#include <cstdint>

#define N_TOK 49
#define C_DIM 96
#define RS 80          // row stride bytes (64B data + 16B pad)
#define QHI 0
#define QLO 5120
#define KHI 10240
#define KLO 15360
#define VHI 20480
#define VLO 25600
#define SMEM_BYTES 30720

__device__ float4 g_bias4[3 * 4 * 7 * 32];  // C-fragment-ordered bias table

// ---------------------------------------------------------------------------
__device__ __forceinline__ uint32_t smem_u32(const void* p) {
    uint32_t a;
    asm("{ .reg .u64 t; cvta.to.shared.u64 t, %1; cvt.u32.u64 %0, t; }" : "=r"(a) : "l"(p));
    return a;
}
__device__ __forceinline__ void ldsm4(uint32_t r[4], uint32_t addr) {
    asm volatile("ldmatrix.sync.aligned.m8n8.x4.shared.b16 {%0,%1,%2,%3}, [%4];"
                 : "=r"(r[0]), "=r"(r[1]), "=r"(r[2]), "=r"(r[3]) : "r"(addr));
}
__device__ __forceinline__ void ldsm4t(uint32_t r[4], uint32_t addr) {
    asm volatile("ldmatrix.sync.aligned.m8n8.x4.trans.shared.b16 {%0,%1,%2,%3}, [%4];"
                 : "=r"(r[0]), "=r"(r[1]), "=r"(r[2]), "=r"(r[3]) : "r"(addr));
}
__device__ __forceinline__ void mma16816(float c[4], const uint32_t a[4],
                                         uint32_t b0, uint32_t b1) {
    asm volatile(
        "mma.sync.aligned.m16n8k16.row.col.f32.bf16.bf16.f32 "
        "{%0,%1,%2,%3}, {%4,%5,%6,%7}, {%8,%9}, {%0,%1,%2,%3};"
        : "+f"(c[0]), "+f"(c[1]), "+f"(c[2]), "+f"(c[3])
        : "r"(a[0]), "r"(a[1]), "r"(a[2]), "r"(a[3]), "r"(b0), "r"(b1));
}
// split (x,y) into packed bf16 hi + bf16 lo (x ~= hi + lo)
__device__ __forceinline__ void cvt2(float x, float y, uint32_t& hi, uint32_t& lo) {
    __nv_bfloat162 h = __floats2bfloat162_rn(x, y);
    float hx = __bfloat162float(__low2bfloat16(h));
    float hy = __bfloat162float(__high2bfloat16(h));
    __nv_bfloat162 l = __floats2bfloat162_rn(x - hx, y - hy);
    hi = *reinterpret_cast<uint32_t*>(&h);
    lo = *reinterpret_cast<uint32_t*>(&l);
}

// ---------------------------------------------------------------------------
// Bias MLP, slice-parallel (8 lanes per position), writing DIRECTLY into the
// C-fragment-ordered table g_bias4. Covers (n,m) in [0,64) x [0,56):
//   m >= 49          -> -1e30 (mask pad cols; j=7 block never read)
//   n >= 49          -> 0     (pad rows, value irrelevant)
//   else             -> relu(rel_pos @ w1 + b1) @ w2 + b2
// ---------------------------------------------------------------------------
__global__ void bias_kernel(const float* __restrict__ rel_pos,
                            const float* __restrict__ w1,
                            const float* __restrict__ b1,
                            const float* __restrict__ w2,
                            const float* __restrict__ b2) {
    int gid = blockIdx.x * blockDim.x + threadIdx.x;
    if (gid >= 64 * 56 * 8) return;
    const int s = gid & 7;          // hidden-slice index
    const int p = gid >> 3;         // position [0, 3584)
    const int n = p / 56;
    const int m = p - n * 56;

    float a0 = 0.f, a1 = 0.f, a2 = 0.f;
    const bool live = (n < N_TOK) && (m < N_TOK);
    if (live) {
        const int idx = n * N_TOK + m;
        const float r0 = rel_pos[2 * idx + 0];
        const float r1 = rel_pos[2 * idx + 1];
        const int j0 = s * 32;
        #pragma unroll 8
        for (int j = j0; j < j0 + 32; ++j) {
            float hj = fmaf(r0, __ldg(w1 + j), fmaf(r1, __ldg(w1 + 256 + j), __ldg(b1 + j)));
            hj = fmaxf(hj, 0.0f);
            a0 = fmaf(hj, __ldg(w2 + j * 3 + 0), a0);
            a1 = fmaf(hj, __ldg(w2 + j * 3 + 1), a1);
            a2 = fmaf(hj, __ldg(w2 + j * 3 + 2), a2);
        }
    }
    // reduce the 8 slices (lanes grouped by 8: xor 1,2,4 stays in-group)
    #pragma unroll
    for (int o = 1; o < 8; o <<= 1) {
        a0 += __shfl_xor_sync(0xffffffffu, a0, o);
        a1 += __shfl_xor_sync(0xffffffffu, a1, o);
        a2 += __shfl_xor_sync(0xffffffffu, a2, o);
    }
    if (s == 0) {
        float v0, v1, v2;
        if (m >= N_TOK)      { v0 = v1 = v2 = -1e30f; }
        else if (n >= N_TOK) { v0 = v1 = v2 = 0.0f; }
        else { v0 = a0 + __ldg(b2 + 0); v1 = a1 + __ldg(b2 + 1); v2 = a2 + __ldg(b2 + 2); }
        // (n,m) -> fragment slot
        const int w    = n >> 4;
        const int half = (n >> 3) & 1;
        const int g    = n & 7;
        const int j    = m >> 3;
        const int tig  = (m & 7) >> 1;
        const int comp = m & 1;
        const int lane4 = g * 4 + tig;
        const int fi    = half * 2 + comp;
        float* base = (float*)g_bias4 + fi;
        base[(((0 * 4 + w) * 7 + j) * 32 + lane4) * 4] = v0;
        base[(((1 * 4 + w) * 7 + j) * 32 + lane4) * 4] = v1;
        base[(((2 * 4 + w) * 7 + j) * 32 + lane4) * 4] = v2;
    }
}

// ---------------------------------------------------------------------------
// CTA = (window, head). 4 warps, warp = 16-row M-tile.
// q/k/v staged to smem as bf16 hi/lo; all fragments via ldmatrix.
// Bias preloaded coalesced (fragment-ordered table) as accumulator init.
// e stays in registers. j=7 all-pad column block skipped.
// ---------------------------------------------------------------------------
__global__ __launch_bounds__(128, 6)
void attn_kernel(const float* __restrict__ q,
                 const float* __restrict__ k,
                 const float* __restrict__ v,
                 float*       __restrict__ out) {
    __shared__ __align__(16) char S[SMEM_BYTES];
    const uint32_t sb = smem_u32(S);

    const int tid  = threadIdx.x;
    const int lane = tid & 31;
    const int warp = tid >> 5;
    const int g    = lane >> 2;
    const int tig  = lane & 3;
    const int r0   = warp * 16;
    const int POFF = (lane & 7) + 8 * ((lane >> 3) & 1);
    const int CG   = lane >> 4;
    const int h    = blockIdx.y;
    const size_t wbase = (size_t)blockIdx.x * (N_TOK * C_DIM);
    const int n1 = r0 + g, n2 = n1 + 8;

    // ---- stage q (scaled), k, v as bf16 hi/lo; zero pad rows 49..63 ----
    {
        const float SC = 0.17677669529663687f;  // 1/sqrt(32)
        #pragma unroll
        for (int it = 0; it < 4; ++it) {
            int i = tid + it * 128;            // 512 = 64 rows x 8 chunks
            int n = i >> 3, c = i & 7;
            uint32_t off = (uint32_t)(n * RS + c * 8);
            uint2 qh = make_uint2(0, 0), ql = qh, kh = qh, kl = qh, vh = qh, vl = qh;
            if (n < N_TOK) {
                size_t ga = wbase + (size_t)n * C_DIM + h * 32 + c * 4;
                float4 xq = *(const float4*)(q + ga);
                float4 xk = *(const float4*)(k + ga);
                float4 xv = *(const float4*)(v + ga);
                cvt2(xq.x * SC, xq.y * SC, qh.x, ql.x);
                cvt2(xq.z * SC, xq.w * SC, qh.y, ql.y);
                cvt2(xk.x, xk.y, kh.x, kl.x);
                cvt2(xk.z, xk.w, kh.y, kl.y);
                cvt2(xv.x, xv.y, vh.x, vl.x);
                cvt2(xv.z, xv.w, vh.y, vl.y);
            }
            *(uint2*)(S + QHI + off) = qh;  *(uint2*)(S + QLO + off) = ql;
            *(uint2*)(S + KHI + off) = kh;  *(uint2*)(S + KLO + off) = kl;
            *(uint2*)(S + VHI + off) = vh;  *(uint2*)(S + VLO + off) = vl;
        }
    }

    // ---- bias -> accumulator init (coalesced fragment-ordered table) ----
    float acc[7][4];
    {
        const float4* bt = g_bias4 + ((h * 4 + warp) * 7) * 32 + lane;
        #pragma unroll
        for (int j = 0; j < 7; ++j) {
            float4 bv = __ldg(bt + j * 32);
            acc[j][0] = bv.x;  acc[j][1] = bv.y;
            acc[j][2] = bv.z;  acc[j][3] = bv.w;
        }
    }
    __syncthreads();

    // ---- q A-fragments via ldmatrix ----
    uint32_t qh0[4], qh1[4], ql0[4], ql1[4];
    {
        const uint32_t aP = sb + QHI + (uint32_t)((r0 + POFF) * RS + CG * 16);
        ldsm4(qh0, aP);
        ldsm4(qh1, aP + 32);
        ldsm4(ql0, aP + (QLO - QHI));
        ldsm4(ql1, aP + (QLO - QHI) + 32);
    }

    // ---- QK: S[64x56] = bias + q @ k^T  (hi*hi + lo*hi + hi*lo) ----
    {
        const uint32_t bP = sb + KHI + (uint32_t)((lane & 7) * RS + (lane >> 3) * 16);
        #pragma unroll
        for (int j = 0; j < 7; ++j) {
            uint32_t bh[4], bl[4];
            ldsm4(bh, bP + (uint32_t)(j * 8 * RS));
            mma16816(acc[j], qh0, bh[0], bh[1]);
            mma16816(acc[j], qh1, bh[2], bh[3]);
            mma16816(acc[j], ql0, bh[0], bh[1]);
            mma16816(acc[j], ql1, bh[2], bh[3]);
            ldsm4(bl, bP + (uint32_t)(j * 8 * RS) + (KLO - KHI));
            mma16816(acc[j], qh0, bl[0], bl[1]);
            mma16816(acc[j], qh1, bl[2], bl[3]);
        }
    }

    // ---- softmax in-place on acc (rows n1, n2; quad-local reductions) ----
    float mx1 = acc[0][0], mx2 = acc[0][2];
    #pragma unroll
    for (int j = 0; j < 7; ++j) {
        mx1 = fmaxf(mx1, fmaxf(acc[j][0], acc[j][1]));
        mx2 = fmaxf(mx2, fmaxf(acc[j][2], acc[j][3]));
    }
    mx1 = fmaxf(mx1, __shfl_xor_sync(0xffffffffu, mx1, 1));
    mx1 = fmaxf(mx1, __shfl_xor_sync(0xffffffffu, mx1, 2));
    mx2 = fmaxf(mx2, __shfl_xor_sync(0xffffffffu, mx2, 1));
    mx2 = fmaxf(mx2, __shfl_xor_sync(0xffffffffu, mx2, 2));
    float sum1 = 0.0f, sum2 = 0.0f;
    #pragma unroll
    for (int j = 0; j < 7; ++j) {
        acc[j][0] = __expf(acc[j][0] - mx1); sum1 += acc[j][0];
        acc[j][1] = __expf(acc[j][1] - mx1); sum1 += acc[j][1];
        acc[j][2] = __expf(acc[j][2] - mx2); sum2 += acc[j][2];
        acc[j][3] = __expf(acc[j][3] - mx2); sum2 += acc[j][3];
    }
    sum1 += __shfl_xor_sync(0xffffffffu, sum1, 1);
    sum1 += __shfl_xor_sync(0xffffffffu, sum1, 2);
    sum2 += __shfl_xor_sync(0xffffffffu, sum2, 1);
    sum2 += __shfl_xor_sync(0xffffffffu, sum2, 2);
    const float rinv1 = 1.0f / sum1;
    const float rinv2 = 1.0f / sum2;

    // ---- e A-fragments in registers (cols 56..63 -> zero) ----
    uint32_t eh[4][4], el[4][4];
    #pragma unroll
    for (int t = 0; t < 3; ++t) {
        cvt2(acc[2*t][0],   acc[2*t][1],   eh[t][0], el[t][0]);
        cvt2(acc[2*t][2],   acc[2*t][3],   eh[t][1], el[t][1]);
        cvt2(acc[2*t+1][0], acc[2*t+1][1], eh[t][2], el[t][2]);
        cvt2(acc[2*t+1][2], acc[2*t+1][3], eh[t][3], el[t][3]);
    }
    cvt2(acc[6][0], acc[6][1], eh[3][0], el[3][0]);
    cvt2(acc[6][2], acc[6][3], eh[3][1], el[3][1]);
    eh[3][2] = 0u; el[3][2] = 0u;
    eh[3][3] = 0u; el[3][3] = 0u;

    // ---- PV: O[64x32] = e @ v  (hi*hi + lo*hi + hi*lo) ----
    float o[4][4];
    #pragma unroll
    for (int j = 0; j < 4; ++j)
        #pragma unroll
        for (int c = 0; c < 4; ++c) o[j][c] = 0.0f;

    {
        const uint32_t vP = sb + VHI + (uint32_t)(POFF * RS + CG * 16);
        #pragma unroll
        for (int t = 0; t < 4; ++t) {
            uint32_t va[4], vb[4];
            const uint32_t base = vP + (uint32_t)(t * 16 * RS);
            ldsm4t(va, base);
            ldsm4t(vb, base + 32);
            mma16816(o[0], eh[t], va[0], va[1]);
            mma16816(o[1], eh[t], va[2], va[3]);
            mma16816(o[2], eh[t], vb[0], vb[1]);
            mma16816(o[3], eh[t], vb[2], vb[3]);
            mma16816(o[0], el[t], va[0], va[1]);
            mma16816(o[1], el[t], va[2], va[3]);
            mma16816(o[2], el[t], vb[0], vb[1]);
            mma16816(o[3], el[t], vb[2], vb[3]);
            ldsm4t(va, base + (VLO - VHI));
            ldsm4t(vb, base + (VLO - VHI) + 32);
            mma16816(o[0], eh[t], va[0], va[1]);
            mma16816(o[1], eh[t], va[2], va[3]);
            mma16816(o[2], eh[t], vb[0], vb[1]);
            mma16816(o[3], eh[t], vb[2], vb[3]);
        }
    }

    // ---- normalize + store ----
    if (n1 < N_TOK) {
        float* op = out + wbase + (size_t)n1 * C_DIM + h * 32;
        #pragma unroll
        for (int j = 0; j < 4; ++j)
            *(float2*)(op + 8 * j + 2 * tig) =
                make_float2(o[j][0] * rinv1, o[j][1] * rinv1);
    }
    if (n2 < N_TOK) {
        float* op = out + wbase + (size_t)n2 * C_DIM + h * 32;
        #pragma unroll
        for (int j = 0; j < 4; ++j)
            *(float2*)(op + 8 * j + 2 * tig) =
                make_float2(o[j][2] * rinv2, o[j][3] * rinv2);
    }
}

// ---------------------------------------------------------------------------
extern "C" void kernel_launch(void* const* d_in, const int* in_sizes, int n_in,
                              void* d_out, int out_size) {
    const float* q       = (const float*)d_in[0];
    const float* k       = (const float*)d_in[1];
    const float* v       = (const float*)d_in[2];
    const float* rel_pos = (const float*)d_in[3];
    const float* w1      = (const float*)d_in[4];
    const float* b1      = (const float*)d_in[5];
    const float* w2      = (const float*)d_in[6];
    const float* b2      = (const float*)d_in[7];
    float* out = (float*)d_out;

    const int nwin = in_sizes[0] / (N_TOK * C_DIM);

    bias_kernel<<<(64 * 56 * 8 + 127) / 128, 128>>>(rel_pos, w1, b1, w2, b2);
    dim3 grid(nwin, 3);
    attn_kernel<<<grid, 128>>>(q, k, v, out);
}